// round 7
// baseline (speedup 1.0000x reference)
#include <cuda_runtime.h>
#include <cstdint>

// ---------------------------------------------------------------------------
// MHA forward: out = (softmax_causal(QK^T/sqrt(D)) V) Wo^T,  also emit attn.
// B=4, L=2048, E=1024, H=16, D=64.
// d_out layout: [out: B*L*E floats][attn: B*H*L*L floats]
// All GEMMs (projections, QK^T, PV, output) on mma.sync m16n8k8 tf32 with
// 3xTF32 error compensation (fp32-grade accuracy).
// ---------------------------------------------------------------------------

constexpr int B_ = 4, L_ = 2048, E_ = 1024, H_ = 16, D_ = 64;
constexpr int BH   = B_ * H_;     // 64
constexpr int NTOK = B_ * L_;     // 8192

// Scratch (static __device__ arrays: allocation-free)
__device__ float g_Q[BH * L_ * D_];
__device__ float g_K[BH * L_ * D_];
__device__ float g_V[BH * L_ * D_];
__device__ float g_Oh[BH * L_ * D_];

// ---------------------------------------------------------------------------
__device__ __forceinline__ uint32_t cvt_tf32(float x) {
    uint32_t r;
    asm("cvt.rna.tf32.f32 %0, %1;" : "=r"(r) : "f"(x));
    return r;
}
__device__ __forceinline__ void split_tf32(float x, uint32_t& hi, uint32_t& lo) {
    hi = cvt_tf32(x);
    lo = cvt_tf32(x - __uint_as_float(hi));
}
__device__ __forceinline__ void mma_tf32(float* c, const uint32_t* a, const uint32_t* b) {
    asm volatile(
        "mma.sync.aligned.m16n8k8.row.col.f32.tf32.tf32.f32 "
        "{%0,%1,%2,%3}, {%4,%5,%6,%7}, {%8,%9}, {%0,%1,%2,%3};"
        : "+f"(c[0]), "+f"(c[1]), "+f"(c[2]), "+f"(c[3])
        : "r"(a[0]), "r"(a[1]), "r"(a[2]), "r"(a[3]), "r"(b[0]), "r"(b[1]));
}

constexpr int BK = 16;
constexpr int APAD = 132;   // [k][m] stride; frag banks conflict-free
constexpr int BPAD = 136;   // [k][n] stride; frag banks conflict-free

// ---------------------------------------------------------------------------
// 3xTF32 tensor-core GEMM body (CTA 128x128, BK=16, 8 warps of 64x32).
// C[m,n] = sum_k A[m,k] * B[n,k]  (B row-major [N,K] = torch Linear weight)
// ---------------------------------------------------------------------------
struct GemmSmem {
    uint32_t Ah[BK][APAD];
    uint32_t Al[BK][APAD];
    uint32_t Bh[BK][BPAD];
    uint32_t Bl[BK][BPAD];
};

template <typename FA, typename FB>
__device__ __forceinline__ void load_chunk(GemmSmem& s, int tid, FA getA, FB getB) {
    const int row = tid >> 1;
    const int kq  = (tid & 1) * 8;
    float4 a0 = *(const float4*)getA(row, kq);
    float4 a1 = *(const float4*)getA(row, kq + 4);
    float4 b0 = *(const float4*)getB(row, kq);
    float4 b1 = *(const float4*)getB(row, kq + 4);
    const float av[8] = {a0.x, a0.y, a0.z, a0.w, a1.x, a1.y, a1.z, a1.w};
    const float bv[8] = {b0.x, b0.y, b0.z, b0.w, b1.x, b1.y, b1.z, b1.w};
#pragma unroll
    for (int t = 0; t < 8; t++) {
        uint32_t hi, lo;
        split_tf32(av[t], hi, lo);
        s.Ah[kq + t][row] = hi;
        s.Al[kq + t][row] = lo;
        split_tf32(bv[t], hi, lo);
        s.Bh[kq + t][row] = hi;
        s.Bl[kq + t][row] = lo;
    }
}

__device__ __forceinline__ void mma_chunk(const GemmSmem& s, int wm, int wn,
                                          int gr, int tig, float acc[4][4][4]) {
#pragma unroll
    for (int ks = 0; ks < 2; ks++) {
        const int kb = ks * 8;
        uint32_t ah[4][4], al[4][4];
#pragma unroll
        for (int i = 0; i < 4; i++) {
            const int r = wm + 16 * i + gr;
            ah[i][0] = s.Ah[kb + tig][r];
            ah[i][1] = s.Ah[kb + tig][r + 8];
            ah[i][2] = s.Ah[kb + tig + 4][r];
            ah[i][3] = s.Ah[kb + tig + 4][r + 8];
            al[i][0] = s.Al[kb + tig][r];
            al[i][1] = s.Al[kb + tig][r + 8];
            al[i][2] = s.Al[kb + tig + 4][r];
            al[i][3] = s.Al[kb + tig + 4][r + 8];
        }
#pragma unroll
        for (int j = 0; j < 4; j++) {
            const int cn = wn + 8 * j + gr;
            uint32_t bh[2], bl[2];
            bh[0] = s.Bh[kb + tig][cn];
            bh[1] = s.Bh[kb + tig + 4][cn];
            bl[0] = s.Bl[kb + tig][cn];
            bl[1] = s.Bl[kb + tig + 4][cn];
#pragma unroll
            for (int i = 0; i < 4; i++) {
                mma_tf32(acc[i][j], ah[i], bh);
                mma_tf32(acc[i][j], ah[i], bl);
                mma_tf32(acc[i][j], al[i], bh);
            }
        }
    }
}

// ---------------------------------------------------------------------------
// Projection GEMM -> per-head layout [B,H,L,D]. blockIdx.z selects q/k/v.
// ---------------------------------------------------------------------------
__global__ __launch_bounds__(256, 2) void proj_tc(
    const float* __restrict__ qin, const float* __restrict__ kin,
    const float* __restrict__ vin,
    const float* __restrict__ Wq, const float* __restrict__ Wk,
    const float* __restrict__ Wv)
{
    const float* X; const float* W; float* Out;
    if (blockIdx.z == 0)      { X = qin; W = Wq; Out = g_Q; }
    else if (blockIdx.z == 1) { X = kin; W = Wk; Out = g_K; }
    else                      { X = vin; W = Wv; Out = g_V; }

    __shared__ GemmSmem s;
    const int tid = threadIdx.x, wid = tid >> 5, lane = tid & 31;
    const int gr = lane >> 2, tig = lane & 3;
    const int wm = (wid & 1) * 64, wn = (wid >> 1) * 32;
    const int m0 = blockIdx.y * 128, n0 = blockIdx.x * 128;

    float acc[4][4][4] = {};
    for (int k0 = 0; k0 < E_; k0 += BK) {
        load_chunk(s, tid,
            [&](int r, int kk) { return &X[(size_t)(m0 + r) * E_ + k0 + kk]; },
            [&](int r, int kk) { return &W[(size_t)(n0 + r) * E_ + k0 + kk]; });
        __syncthreads();
        mma_chunk(s, wm, wn, gr, tig, acc);
        __syncthreads();
    }

#pragma unroll
    for (int i = 0; i < 4; i++) {
        const int m_a = m0 + wm + 16 * i + gr;
        const int m_b = m_a + 8;
        const int ba = m_a >> 11, la = m_a & (L_ - 1);
        const int bb = m_b >> 11, lb = m_b & (L_ - 1);
#pragma unroll
        for (int j = 0; j < 4; j++) {
            const int col = n0 + wn + 8 * j + 2 * tig;
            const int h = col >> 6, d = col & 63;
            *(float2*)&Out[((size_t)(ba * H_ + h) * L_ + la) * D_ + d] =
                make_float2(acc[i][j][0], acc[i][j][1]);
            *(float2*)&Out[((size_t)(bb * H_ + h) * L_ + lb) * D_ + d] =
                make_float2(acc[i][j][2], acc[i][j][3]);
        }
    }
}

// ---------------------------------------------------------------------------
// Output projection: out[m,n] = sum_k Oh[m,k] * Wo[n,k].
// ---------------------------------------------------------------------------
__global__ __launch_bounds__(256, 2) void outproj_tc(
    const float* __restrict__ Wo, float* __restrict__ out)
{
    __shared__ GemmSmem s;
    const int tid = threadIdx.x, wid = tid >> 5, lane = tid & 31;
    const int gr = lane >> 2, tig = lane & 3;
    const int wm = (wid & 1) * 64, wn = (wid >> 1) * 32;
    const int m0 = blockIdx.y * 128, n0 = blockIdx.x * 128;

    float acc[4][4][4] = {};
    for (int k0 = 0; k0 < E_; k0 += BK) {
        load_chunk(s, tid,
            [&](int r, int kk) {
                int m = m0 + r, k = k0 + kk;
                int b = m >> 11, l = m & (L_ - 1);
                return &g_Oh[((size_t)(b * H_ + (k >> 6)) * L_ + l) * D_ + (k & 63)];
            },
            [&](int r, int kk) { return &Wo[(size_t)(n0 + r) * E_ + k0 + kk]; });
        __syncthreads();
        mma_chunk(s, wm, wn, gr, tig, acc);
        __syncthreads();
    }

#pragma unroll
    for (int i = 0; i < 4; i++) {
        const int m_a = m0 + wm + 16 * i + gr;
#pragma unroll
        for (int j = 0; j < 4; j++) {
            const int col = n0 + wn + 8 * j + 2 * tig;
            *(float2*)&out[(size_t)m_a * E_ + col] =
                make_float2(acc[i][j][0], acc[i][j][1]);
            *(float2*)&out[(size_t)(m_a + 8) * E_ + col] =
                make_float2(acc[i][j][2], acc[i][j][3]);
        }
    }
}

// ---------------------------------------------------------------------------
// Tensor-core fused causal attention.
// CTA = 128 Q-rows x 64-col steps; 8 warps, warp tile m16 x n64.
// Q held in registers as pre-split tf32 A-frags. K/V tiles in smem in natural
// [row][d] layout, stride 68 (bank-conflict-free frag loads, verified).
// p = exp(QK^T/8) (no max-subtraction, exact after /l rescale); unnormalized
// P -> smem (PV A-frags) + gmem; l row-sums in registers; O = PV normalized
// at the end; P normalized in-place + upper triangle zero-filled.
// ---------------------------------------------------------------------------
__global__ __launch_bounds__(256) void attn_tc(float* __restrict__ attn_base)
{
    extern __shared__ float sm[];
    float* Ks = sm;            // [64][68]
    float* Vs = sm + 4352;     // [64][68]
    float* Ps = sm + 8704;     // [128][68]
    float* sl = sm + 17408;    // [128]

    const int bh = blockIdx.y;
    const int it = (int)gridDim.x - 1 - (int)blockIdx.x;   // heavy tiles first
    const int q0 = it * 128;
    const int tid = threadIdx.x, wid = tid >> 5, lane = tid & 31;
    const int gr = lane >> 2, tig = lane & 3;
    const int wm = wid * 16;

    const float* Qp = g_Q + (size_t)bh * L_ * D_;
    const float* Kp = g_K + (size_t)bh * L_ * D_;
    const float* Vp = g_V + (size_t)bh * L_ * D_;
    float* attn = attn_base + (size_t)bh * L_ * L_;

    // Q A-fragments (whole kernel), 3xTF32 split
    uint32_t qh[8][4], ql[8][4];
    {
        const int r0 = q0 + wm + gr, r1 = r0 + 8;
#pragma unroll
        for (int ks = 0; ks < 8; ks++) {
            float x0 = Qp[(size_t)r0 * D_ + ks * 8 + tig];
            float x1 = Qp[(size_t)r1 * D_ + ks * 8 + tig];
            float x2 = Qp[(size_t)r0 * D_ + ks * 8 + tig + 4];
            float x3 = Qp[(size_t)r1 * D_ + ks * 8 + tig + 4];
            split_tf32(x0, qh[ks][0], ql[ks][0]);
            split_tf32(x1, qh[ks][1], ql[ks][1]);
            split_tf32(x2, qh[ks][2], ql[ks][2]);
            split_tf32(x3, qh[ks][3], ql[ks][3]);
        }
    }

    float l0 = 0.f, l1 = 0.f;
    float oa[8][4] = {};                 // O frags over d (8 n-tiles of 8)
    const int ntiles = 2 * it + 2;
    const float scale = 0.125f;          // 1/sqrt(64)
    const int grow0 = q0 + wm + gr, grow1 = grow0 + 8;

    for (int jt = 0; jt < ntiles; jt++) {
        __syncthreads();   // prev iter done reading Ks/Vs/Ps
#pragma unroll
        for (int c = 0; c < 4; c++) {
            int id = c * 256 + tid;
            int r = id >> 4, d4 = (id & 15) << 2;
            *(float4*)&Ks[r * 68 + d4] =
                *(const float4*)&Kp[(size_t)(jt * 64 + r) * D_ + d4];
            *(float4*)&Vs[r * 68 + d4] =
                *(const float4*)&Vp[(size_t)(jt * 64 + r) * D_ + d4];
        }
        __syncthreads();

        // S = Q K^T (3xTF32); B-frag: b0 = K[8nt+gr][kb+tig] (banks 4gr+tig)
        float sc[8][4];
#pragma unroll
        for (int nt = 0; nt < 8; nt++)
            sc[nt][0] = sc[nt][1] = sc[nt][2] = sc[nt][3] = 0.f;
#pragma unroll
        for (int ks = 0; ks < 8; ks++) {
#pragma unroll
            for (int nt = 0; nt < 8; nt++) {
                float b0f = Ks[(nt * 8 + gr) * 68 + ks * 8 + tig];
                float b1f = Ks[(nt * 8 + gr) * 68 + ks * 8 + tig + 4];
                uint32_t bh0, bl0, bh1, bl1;
                split_tf32(b0f, bh0, bl0);
                split_tf32(b1f, bh1, bl1);
                uint32_t bhv[2] = {bh0, bh1}, blv[2] = {bl0, bl1};
                mma_tf32(sc[nt], qh[ks], bhv);
                mma_tf32(sc[nt], qh[ks], blv);
                mma_tf32(sc[nt], ql[ks], bhv);
            }
        }

        // exp + causal mask + accumulate l + stage P in smem
        float pl0 = 0.f, pl1 = 0.f;
#pragma unroll
        for (int nt = 0; nt < 8; nt++) {
            int jc = jt * 64 + nt * 8 + 2 * tig;
            float p0 = __expf(sc[nt][0] * scale); if (jc     > grow0) p0 = 0.f;
            float p1 = __expf(sc[nt][1] * scale); if (jc + 1 > grow0) p1 = 0.f;
            float p2 = __expf(sc[nt][2] * scale); if (jc     > grow1) p2 = 0.f;
            float p3 = __expf(sc[nt][3] * scale); if (jc + 1 > grow1) p3 = 0.f;
            pl0 += p0 + p1;
            pl1 += p2 + p3;
            *(float2*)&Ps[(wm + gr) * 68 + nt * 8 + 2 * tig]     = make_float2(p0, p1);
            *(float2*)&Ps[(wm + gr + 8) * 68 + nt * 8 + 2 * tig] = make_float2(p2, p3);
        }
        pl0 += __shfl_xor_sync(0xffffffffu, pl0, 1);
        pl0 += __shfl_xor_sync(0xffffffffu, pl0, 2);
        pl1 += __shfl_xor_sync(0xffffffffu, pl1, 1);
        pl1 += __shfl_xor_sync(0xffffffffu, pl1, 2);
        l0 += pl0; l1 += pl1;
        __syncthreads();   // Ps visible

        // O += P V (3xTF32); A-frag from Ps (banks 4gr+tig),
        // B-frag b0 = V[kb+tig][8nt+gr] (banks 4tig+gr) — natural layout.
#pragma unroll
        for (int ks = 0; ks < 8; ks++) {
            uint32_t ph[4], plo[4];
            float a0 = Ps[(wm + gr) * 68 + ks * 8 + tig];
            float a1 = Ps[(wm + gr + 8) * 68 + ks * 8 + tig];
            float a2 = Ps[(wm + gr) * 68 + ks * 8 + tig + 4];
            float a3 = Ps[(wm + gr + 8) * 68 + ks * 8 + tig + 4];
            split_tf32(a0, ph[0], plo[0]);
            split_tf32(a1, ph[1], plo[1]);
            split_tf32(a2, ph[2], plo[2]);
            split_tf32(a3, ph[3], plo[3]);
#pragma unroll
            for (int nt = 0; nt < 8; nt++) {
                float b0f = Vs[(ks * 8 + tig) * 68 + nt * 8 + gr];
                float b1f = Vs[(ks * 8 + tig + 4) * 68 + nt * 8 + gr];
                uint32_t bh0, bl0, bh1, bl1;
                split_tf32(b0f, bh0, bl0);
                split_tf32(b1f, bh1, bl1);
                uint32_t bhv[2] = {bh0, bh1}, blv[2] = {bl0, bl1};
                mma_tf32(oa[nt], ph, bhv);
                mma_tf32(oa[nt], ph, blv);
                mma_tf32(oa[nt], plo, bhv);
            }
        }

        // write unnormalized P tile to gmem (coalesced float4)
#pragma unroll
        for (int c = 0; c < 8; c++) {
            int id = c * 256 + tid;
            int r = id >> 4, c4 = (id & 15) << 2;
            *(float4*)&attn[(size_t)(q0 + r) * L_ + jt * 64 + c4] =
                *(const float4*)&Ps[r * 68 + c4];
        }
    }

    const float inv0 = 1.f / l0, inv1 = 1.f / l1;
    if (tig == 0) {
        sl[wm + gr] = inv0;
        sl[wm + gr + 8] = inv1;
    }
    // normalized O -> scratch [B,H,L,D]
#pragma unroll
    for (int nt = 0; nt < 8; nt++) {
        *(float2*)&g_Oh[((size_t)bh * L_ + grow0) * D_ + nt * 8 + 2 * tig] =
            make_float2(oa[nt][0] * inv0, oa[nt][1] * inv0);
        *(float2*)&g_Oh[((size_t)bh * L_ + grow1) * D_ + nt * 8 + 2 * tig] =
            make_float2(oa[nt][2] * inv1, oa[nt][3] * inv1);
    }
    __syncthreads();   // sl visible

    // normalize lower tiles in place; zero-fill upper triangle
    for (int j2 = 0; j2 < ntiles; j2++) {
#pragma unroll
        for (int c = 0; c < 8; c++) {
            int id = c * 256 + tid;
            int r = id >> 4, c4 = (id & 15) << 2;
            float inv = sl[r];
            float* p = &attn[(size_t)(q0 + r) * L_ + j2 * 64 + c4];
            float4 v = *(float4*)p;
            v.x *= inv; v.y *= inv; v.z *= inv; v.w *= inv;
            *(float4*)p = v;
        }
    }
    const float4 z4 = make_float4(0.f, 0.f, 0.f, 0.f);
    for (int j2 = ntiles; j2 < L_ / 64; j2++) {
#pragma unroll
        for (int c = 0; c < 8; c++) {
            int id = c * 256 + tid;
            int r = id >> 4, c4 = (id & 15) << 2;
            *(float4*)&attn[(size_t)(q0 + r) * L_ + j2 * 64 + c4] = z4;
        }
    }
}

constexpr int ATTN_SMEM = (17408 + 128) * 4;   // ~68.6 KB dynamic

// ---------------------------------------------------------------------------
extern "C" void kernel_launch(void* const* d_in, const int* in_sizes, int n_in,
                              void* d_out, int out_size)
{
    const float* qkv[3] = {nullptr, nullptr, nullptr};
    const float* Ws[4]  = {nullptr, nullptr, nullptr, nullptr};
    int nqkv = 0, nw = 0;
    for (int i = 0; i < n_in; i++) {
        if (in_sizes[i] == NTOK * E_) { if (nqkv < 3) qkv[nqkv++] = (const float*)d_in[i]; }
        else if (in_sizes[i] == E_ * E_) { if (nw < 4) Ws[nw++] = (const float*)d_in[i]; }
    }
    const float* q  = qkv[0]; const float* k  = qkv[1]; const float* v  = qkv[2];
    const float* Wq = Ws[0];  const float* Wk = Ws[1];
    const float* Wv = Ws[2];  const float* Wo = Ws[3];

    float* out  = (float*)d_out;
    float* attn = out + (size_t)B_ * L_ * E_;

    cudaFuncSetAttribute(attn_tc, cudaFuncAttributeMaxDynamicSharedMemorySize,
                         ATTN_SMEM);

    proj_tc<<<dim3(E_ / 128, NTOK / 128, 3), 256>>>(q, k, v, Wq, Wk, Wv);
    attn_tc<<<dim3(L_ / 128, BH), 256, ATTN_SMEM>>>(attn);
    outproj_tc<<<dim3(E_ / 128, NTOK / 128), 256>>>(Wo, out);
}

// round 8
// speedup vs baseline: 1.1620x; 1.1620x over previous
#include <cuda_runtime.h>
#include <cstdint>

// ---------------------------------------------------------------------------
// MHA forward: out = (softmax_causal(QK^T/sqrt(D)) V) Wo^T,  also emit attn.
// B=4, L=2048, E=1024, H=16, D=64.
// d_out layout: [out: B*L*E floats][attn: B*H*L*L floats]
// All GEMMs on mma.sync m16n8k8 tf32 with 3xTF32 compensation.
// R8: attention pre-splits K/V/P into hi/lo smem ONCE (R7 re-split per warp
// per inner iteration -> scalar-issue-bound). K/V share a buffer: 105KB smem,
// 2 CTAs/SM.
// ---------------------------------------------------------------------------

constexpr int B_ = 4, L_ = 2048, E_ = 1024, H_ = 16, D_ = 64;
constexpr int BH   = B_ * H_;     // 64
constexpr int NTOK = B_ * L_;     // 8192

// Scratch (static __device__ arrays: allocation-free)
__device__ float g_Q[BH * L_ * D_];
__device__ float g_K[BH * L_ * D_];
__device__ float g_V[BH * L_ * D_];
__device__ float g_Oh[BH * L_ * D_];

// ---------------------------------------------------------------------------
__device__ __forceinline__ uint32_t cvt_tf32(float x) {
    uint32_t r;
    asm("cvt.rna.tf32.f32 %0, %1;" : "=r"(r) : "f"(x));
    return r;
}
__device__ __forceinline__ void split_tf32(float x, uint32_t& hi, uint32_t& lo) {
    hi = cvt_tf32(x);
    lo = cvt_tf32(x - __uint_as_float(hi));
}
__device__ __forceinline__ void mma_tf32(float* c, const uint32_t* a, const uint32_t* b) {
    asm volatile(
        "mma.sync.aligned.m16n8k8.row.col.f32.tf32.tf32.f32 "
        "{%0,%1,%2,%3}, {%4,%5,%6,%7}, {%8,%9}, {%0,%1,%2,%3};"
        : "+f"(c[0]), "+f"(c[1]), "+f"(c[2]), "+f"(c[3])
        : "r"(a[0]), "r"(a[1]), "r"(a[2]), "r"(a[3]), "r"(b[0]), "r"(b[1]));
}

constexpr int BK = 16;
constexpr int APAD = 132;
constexpr int BPAD = 136;

// ---------------------------------------------------------------------------
// 3xTF32 tensor-core GEMM body (CTA 128x128, BK=16, 8 warps of 64x32).
// ---------------------------------------------------------------------------
struct GemmSmem {
    uint32_t Ah[BK][APAD];
    uint32_t Al[BK][APAD];
    uint32_t Bh[BK][BPAD];
    uint32_t Bl[BK][BPAD];
};

template <typename FA, typename FB>
__device__ __forceinline__ void load_chunk(GemmSmem& s, int tid, FA getA, FB getB) {
    const int row = tid >> 1;
    const int kq  = (tid & 1) * 8;
    float4 a0 = *(const float4*)getA(row, kq);
    float4 a1 = *(const float4*)getA(row, kq + 4);
    float4 b0 = *(const float4*)getB(row, kq);
    float4 b1 = *(const float4*)getB(row, kq + 4);
    const float av[8] = {a0.x, a0.y, a0.z, a0.w, a1.x, a1.y, a1.z, a1.w};
    const float bv[8] = {b0.x, b0.y, b0.z, b0.w, b1.x, b1.y, b1.z, b1.w};
#pragma unroll
    for (int t = 0; t < 8; t++) {
        uint32_t hi, lo;
        split_tf32(av[t], hi, lo);
        s.Ah[kq + t][row] = hi;
        s.Al[kq + t][row] = lo;
        split_tf32(bv[t], hi, lo);
        s.Bh[kq + t][row] = hi;
        s.Bl[kq + t][row] = lo;
    }
}

__device__ __forceinline__ void mma_chunk(const GemmSmem& s, int wm, int wn,
                                          int gr, int tig, float acc[4][4][4]) {
#pragma unroll
    for (int ks = 0; ks < 2; ks++) {
        const int kb = ks * 8;
        uint32_t ah[4][4], al[4][4];
#pragma unroll
        for (int i = 0; i < 4; i++) {
            const int r = wm + 16 * i + gr;
            ah[i][0] = s.Ah[kb + tig][r];
            ah[i][1] = s.Ah[kb + tig][r + 8];
            ah[i][2] = s.Ah[kb + tig + 4][r];
            ah[i][3] = s.Ah[kb + tig + 4][r + 8];
            al[i][0] = s.Al[kb + tig][r];
            al[i][1] = s.Al[kb + tig][r + 8];
            al[i][2] = s.Al[kb + tig + 4][r];
            al[i][3] = s.Al[kb + tig + 4][r + 8];
        }
#pragma unroll
        for (int j = 0; j < 4; j++) {
            const int cn = wn + 8 * j + gr;
            uint32_t bh[2], bl[2];
            bh[0] = s.Bh[kb + tig][cn];
            bh[1] = s.Bh[kb + tig + 4][cn];
            bl[0] = s.Bl[kb + tig][cn];
            bl[1] = s.Bl[kb + tig + 4][cn];
#pragma unroll
            for (int i = 0; i < 4; i++) {
                mma_tf32(acc[i][j], ah[i], bh);
                mma_tf32(acc[i][j], ah[i], bl);
                mma_tf32(acc[i][j], al[i], bh);
            }
        }
    }
}

// ---------------------------------------------------------------------------
// Projection GEMM -> per-head layout [B,H,L,D]. blockIdx.z selects q/k/v.
// ---------------------------------------------------------------------------
__global__ __launch_bounds__(256, 2) void proj_tc(
    const float* __restrict__ qin, const float* __restrict__ kin,
    const float* __restrict__ vin,
    const float* __restrict__ Wq, const float* __restrict__ Wk,
    const float* __restrict__ Wv)
{
    const float* X; const float* W; float* Out;
    if (blockIdx.z == 0)      { X = qin; W = Wq; Out = g_Q; }
    else if (blockIdx.z == 1) { X = kin; W = Wk; Out = g_K; }
    else                      { X = vin; W = Wv; Out = g_V; }

    __shared__ GemmSmem s;
    const int tid = threadIdx.x, wid = tid >> 5, lane = tid & 31;
    const int gr = lane >> 2, tig = lane & 3;
    const int wm = (wid & 1) * 64, wn = (wid >> 1) * 32;
    const int m0 = blockIdx.y * 128, n0 = blockIdx.x * 128;

    float acc[4][4][4] = {};
    for (int k0 = 0; k0 < E_; k0 += BK) {
        load_chunk(s, tid,
            [&](int r, int kk) { return &X[(size_t)(m0 + r) * E_ + k0 + kk]; },
            [&](int r, int kk) { return &W[(size_t)(n0 + r) * E_ + k0 + kk]; });
        __syncthreads();
        mma_chunk(s, wm, wn, gr, tig, acc);
        __syncthreads();
    }

#pragma unroll
    for (int i = 0; i < 4; i++) {
        const int m_a = m0 + wm + 16 * i + gr;
        const int m_b = m_a + 8;
        const int ba = m_a >> 11, la = m_a & (L_ - 1);
        const int bb = m_b >> 11, lb = m_b & (L_ - 1);
#pragma unroll
        for (int j = 0; j < 4; j++) {
            const int col = n0 + wn + 8 * j + 2 * tig;
            const int h = col >> 6, d = col & 63;
            *(float2*)&Out[((size_t)(ba * H_ + h) * L_ + la) * D_ + d] =
                make_float2(acc[i][j][0], acc[i][j][1]);
            *(float2*)&Out[((size_t)(bb * H_ + h) * L_ + lb) * D_ + d] =
                make_float2(acc[i][j][2], acc[i][j][3]);
        }
    }
}

// ---------------------------------------------------------------------------
// Output projection: out[m,n] = sum_k Oh[m,k] * Wo[n,k].
// ---------------------------------------------------------------------------
__global__ __launch_bounds__(256, 2) void outproj_tc(
    const float* __restrict__ Wo, float* __restrict__ out)
{
    __shared__ GemmSmem s;
    const int tid = threadIdx.x, wid = tid >> 5, lane = tid & 31;
    const int gr = lane >> 2, tig = lane & 3;
    const int wm = (wid & 1) * 64, wn = (wid >> 1) * 32;
    const int m0 = blockIdx.y * 128, n0 = blockIdx.x * 128;

    float acc[4][4][4] = {};
    for (int k0 = 0; k0 < E_; k0 += BK) {
        load_chunk(s, tid,
            [&](int r, int kk) {
                int m = m0 + r, k = k0 + kk;
                int b = m >> 11, l = m & (L_ - 1);
                return &g_Oh[((size_t)(b * H_ + (k >> 6)) * L_ + l) * D_ + (k & 63)];
            },
            [&](int r, int kk) { return &Wo[(size_t)(n0 + r) * E_ + k0 + kk]; });
        __syncthreads();
        mma_chunk(s, wm, wn, gr, tig, acc);
        __syncthreads();
    }

#pragma unroll
    for (int i = 0; i < 4; i++) {
        const int m_a = m0 + wm + 16 * i + gr;
#pragma unroll
        for (int j = 0; j < 4; j++) {
            const int col = n0 + wn + 8 * j + 2 * tig;
            *(float2*)&out[(size_t)m_a * E_ + col] =
                make_float2(acc[i][j][0], acc[i][j][1]);
            *(float2*)&out[(size_t)(m_a + 8) * E_ + col] =
                make_float2(acc[i][j][2], acc[i][j][3]);
        }
    }
}

// ---------------------------------------------------------------------------
// Tensor-core fused causal attention, pre-split operands.
// CTA = 128 Q-rows; 8 warps, warp tile m16 x n64; jt-steps of 64 K-columns.
// smem: KVh/KVl [64][68] (K during QK, then refilled with V for PV),
//       Phi/Plo [128][68] (P hi/lo staged by exp phase for PV A-frags).
// Q kept as fp32 frags in regs, split per ks (reg budget). Unnormalized P
// written straight from regs; in-place normalize + upper zero-fill at end.
// ---------------------------------------------------------------------------
__global__ __launch_bounds__(256, 2) void attn_tc(float* __restrict__ attn_base)
{
    extern __shared__ uint32_t usm[];
    uint32_t* KVh = usm;            // [64*68]
    uint32_t* KVl = usm + 4352;
    uint32_t* Phi = usm + 8704;     // [128*68]
    uint32_t* Plo = usm + 17408;
    float*    sl  = (float*)(usm + 26112);   // [128]

    const int bh = blockIdx.y;
    const int it = (int)gridDim.x - 1 - (int)blockIdx.x;   // heavy tiles first
    const int q0 = it * 128;
    const int tid = threadIdx.x, wid = tid >> 5, lane = tid & 31;
    const int gr = lane >> 2, tig = lane & 3;
    const int wm = wid * 16;

    const float* Qp = g_Q + (size_t)bh * L_ * D_;
    const float* Kp = g_K + (size_t)bh * L_ * D_;
    const float* Vp = g_V + (size_t)bh * L_ * D_;
    float* attn = attn_base + (size_t)bh * L_ * L_;

    // Q A-fragments in fp32 (split on the fly per ks to stay <=128 regs)
    float qf[8][4];
    {
        const int r0 = q0 + wm + gr, r1 = r0 + 8;
#pragma unroll
        for (int ks = 0; ks < 8; ks++) {
            qf[ks][0] = Qp[(size_t)r0 * D_ + ks * 8 + tig];
            qf[ks][1] = Qp[(size_t)r1 * D_ + ks * 8 + tig];
            qf[ks][2] = Qp[(size_t)r0 * D_ + ks * 8 + tig + 4];
            qf[ks][3] = Qp[(size_t)r1 * D_ + ks * 8 + tig + 4];
        }
    }

    float l0 = 0.f, l1 = 0.f;
    float oa[8][4] = {};
    const int ntiles = 2 * it + 2;
    const float scale = 0.125f;          // 1/sqrt(64)
    const int grow0 = q0 + wm + gr, grow1 = grow0 + 8;

    for (int jt = 0; jt < ntiles; jt++) {
        __syncthreads();   // prev PV done reading KV(V)/Phi/Plo
        // K tile -> split hi/lo smem (each element split once, natural [r][d])
#pragma unroll
        for (int c = 0; c < 4; c++) {
            int id = c * 256 + tid;
            int r = id >> 4, d4 = (id & 15) << 2;
            float4 kv = *(const float4*)&Kp[(size_t)(jt * 64 + r) * D_ + d4];
            uint32_t hi, lo;
            split_tf32(kv.x, hi, lo); KVh[r * 68 + d4 + 0] = hi; KVl[r * 68 + d4 + 0] = lo;
            split_tf32(kv.y, hi, lo); KVh[r * 68 + d4 + 1] = hi; KVl[r * 68 + d4 + 1] = lo;
            split_tf32(kv.z, hi, lo); KVh[r * 68 + d4 + 2] = hi; KVl[r * 68 + d4 + 2] = lo;
            split_tf32(kv.w, hi, lo); KVh[r * 68 + d4 + 3] = hi; KVl[r * 68 + d4 + 3] = lo;
        }
        __syncthreads();

        // S = Q K^T (3xTF32); B-frags are bare LDS of pre-split words
        float sc[8][4];
#pragma unroll
        for (int nt = 0; nt < 8; nt++)
            sc[nt][0] = sc[nt][1] = sc[nt][2] = sc[nt][3] = 0.f;
#pragma unroll
        for (int ks = 0; ks < 8; ks++) {
            uint32_t ah[4], al[4];
            split_tf32(qf[ks][0], ah[0], al[0]);
            split_tf32(qf[ks][1], ah[1], al[1]);
            split_tf32(qf[ks][2], ah[2], al[2]);
            split_tf32(qf[ks][3], ah[3], al[3]);
#pragma unroll
            for (int nt = 0; nt < 8; nt++) {
                const int rb = (nt * 8 + gr) * 68 + ks * 8 + tig;
                uint32_t bhv[2] = {KVh[rb], KVh[rb + 4]};
                uint32_t blv[2] = {KVl[rb], KVl[rb + 4]};
                mma_tf32(sc[nt], ah, bhv);
                mma_tf32(sc[nt], ah, blv);
                mma_tf32(sc[nt], al, bhv);
            }
        }

        // exp + causal mask; accumulate l; stage P hi/lo; write unnorm P
        float pl0 = 0.f, pl1 = 0.f;
#pragma unroll
        for (int nt = 0; nt < 8; nt++) {
            int jc = jt * 64 + nt * 8 + 2 * tig;
            float p0 = __expf(sc[nt][0] * scale); if (jc     > grow0) p0 = 0.f;
            float p1 = __expf(sc[nt][1] * scale); if (jc + 1 > grow0) p1 = 0.f;
            float p2 = __expf(sc[nt][2] * scale); if (jc     > grow1) p2 = 0.f;
            float p3 = __expf(sc[nt][3] * scale); if (jc + 1 > grow1) p3 = 0.f;
            pl0 += p0 + p1;
            pl1 += p2 + p3;
            uint32_t h0, l0_, h1, l1_, h2, l2_, h3, l3_;
            split_tf32(p0, h0, l0_); split_tf32(p1, h1, l1_);
            split_tf32(p2, h2, l2_); split_tf32(p3, h3, l3_);
            const int pa = (wm + gr) * 68 + nt * 8 + 2 * tig;
            const int pb = (wm + gr + 8) * 68 + nt * 8 + 2 * tig;
            *(uint2*)&Phi[pa] = make_uint2(h0, h1);
            *(uint2*)&Plo[pa] = make_uint2(l0_, l1_);
            *(uint2*)&Phi[pb] = make_uint2(h2, h3);
            *(uint2*)&Plo[pb] = make_uint2(l2_, l3_);
            *(float2*)&attn[(size_t)grow0 * L_ + jc] = make_float2(p0, p1);
            *(float2*)&attn[(size_t)grow1 * L_ + jc] = make_float2(p2, p3);
        }
        pl0 += __shfl_xor_sync(0xffffffffu, pl0, 1);
        pl0 += __shfl_xor_sync(0xffffffffu, pl0, 2);
        pl1 += __shfl_xor_sync(0xffffffffu, pl1, 1);
        pl1 += __shfl_xor_sync(0xffffffffu, pl1, 2);
        l0 += pl0; l1 += pl1;
        __syncthreads();   // all QK reads of KV(K) done; Phi/Plo visible

        // V tile -> same hi/lo buffers
#pragma unroll
        for (int c = 0; c < 4; c++) {
            int id = c * 256 + tid;
            int r = id >> 4, d4 = (id & 15) << 2;
            float4 vv = *(const float4*)&Vp[(size_t)(jt * 64 + r) * D_ + d4];
            uint32_t hi, lo;
            split_tf32(vv.x, hi, lo); KVh[r * 68 + d4 + 0] = hi; KVl[r * 68 + d4 + 0] = lo;
            split_tf32(vv.y, hi, lo); KVh[r * 68 + d4 + 1] = hi; KVl[r * 68 + d4 + 1] = lo;
            split_tf32(vv.z, hi, lo); KVh[r * 68 + d4 + 2] = hi; KVl[r * 68 + d4 + 2] = lo;
            split_tf32(vv.w, hi, lo); KVh[r * 68 + d4 + 3] = hi; KVl[r * 68 + d4 + 3] = lo;
        }
        __syncthreads();

        // O += P V (3xTF32); all frag loads are bare LDS
#pragma unroll
        for (int ks = 0; ks < 8; ks++) {
            const int a0 = (wm + gr) * 68 + ks * 8 + tig;
            const int a1 = (wm + gr + 8) * 68 + ks * 8 + tig;
            uint32_t ph[4]  = {Phi[a0], Phi[a1], Phi[a0 + 4], Phi[a1 + 4]};
            uint32_t plo[4] = {Plo[a0], Plo[a1], Plo[a0 + 4], Plo[a1 + 4]};
#pragma unroll
            for (int nt = 0; nt < 8; nt++) {
                const int vb0 = (ks * 8 + tig) * 68 + nt * 8 + gr;
                const int vb1 = (ks * 8 + tig + 4) * 68 + nt * 8 + gr;
                uint32_t bhv[2] = {KVh[vb0], KVh[vb1]};
                uint32_t blv[2] = {KVl[vb0], KVl[vb1]};
                mma_tf32(oa[nt], ph, bhv);
                mma_tf32(oa[nt], ph, blv);
                mma_tf32(oa[nt], plo, bhv);
            }
        }
    }

    const float inv0 = 1.f / l0, inv1 = 1.f / l1;
    if (tig == 0) {
        sl[wm + gr] = inv0;
        sl[wm + gr + 8] = inv1;
    }
    // normalized O -> scratch [B,H,L,D]
#pragma unroll
    for (int nt = 0; nt < 8; nt++) {
        *(float2*)&g_Oh[((size_t)bh * L_ + grow0) * D_ + nt * 8 + 2 * tig] =
            make_float2(oa[nt][0] * inv0, oa[nt][1] * inv0);
        *(float2*)&g_Oh[((size_t)bh * L_ + grow1) * D_ + nt * 8 + 2 * tig] =
            make_float2(oa[nt][2] * inv1, oa[nt][3] * inv1);
    }
    __syncthreads();   // sl visible (and all P gmem writes done CTA-wide)

    // normalize lower tiles in place; zero-fill upper triangle
    for (int j2 = 0; j2 < ntiles; j2++) {
#pragma unroll
        for (int c = 0; c < 8; c++) {
            int id = c * 256 + tid;
            int r = id >> 4, c4 = (id & 15) << 2;
            float inv = sl[r];
            float* p = &attn[(size_t)(q0 + r) * L_ + j2 * 64 + c4];
            float4 v = *(float4*)p;
            v.x *= inv; v.y *= inv; v.z *= inv; v.w *= inv;
            *(float4*)p = v;
        }
    }
    const float4 z4 = make_float4(0.f, 0.f, 0.f, 0.f);
    for (int j2 = ntiles; j2 < L_ / 64; j2++) {
#pragma unroll
        for (int c = 0; c < 8; c++) {
            int id = c * 256 + tid;
            int r = id >> 4, c4 = (id & 15) << 2;
            *(float4*)&attn[(size_t)(q0 + r) * L_ + j2 * 64 + c4] = z4;
        }
    }
}

constexpr int ATTN_SMEM = (26112 + 128) * 4 + 256;   // ~105KB dynamic

// ---------------------------------------------------------------------------
extern "C" void kernel_launch(void* const* d_in, const int* in_sizes, int n_in,
                              void* d_out, int out_size)
{
    const float* qkv[3] = {nullptr, nullptr, nullptr};
    const float* Ws[4]  = {nullptr, nullptr, nullptr, nullptr};
    int nqkv = 0, nw = 0;
    for (int i = 0; i < n_in; i++) {
        if (in_sizes[i] == NTOK * E_) { if (nqkv < 3) qkv[nqkv++] = (const float*)d_in[i]; }
        else if (in_sizes[i] == E_ * E_) { if (nw < 4) Ws[nw++] = (const float*)d_in[i]; }
    }
    const float* q  = qkv[0]; const float* k  = qkv[1]; const float* v  = qkv[2];
    const float* Wq = Ws[0];  const float* Wk = Ws[1];
    const float* Wv = Ws[2];  const float* Wo = Ws[3];

    float* out  = (float*)d_out;
    float* attn = out + (size_t)B_ * L_ * E_;

    cudaFuncSetAttribute(attn_tc, cudaFuncAttributeMaxDynamicSharedMemorySize,
                         ATTN_SMEM);

    proj_tc<<<dim3(E_ / 128, NTOK / 128, 3), 256>>>(q, k, v, Wq, Wk, Wv);
    attn_tc<<<dim3(L_ / 128, BH), 256, ATTN_SMEM>>>(attn);
    outproj_tc<<<dim3(E_ / 128, NTOK / 128), 256>>>(Wo, out);
}

// round 9
// speedup vs baseline: 1.7432x; 1.5002x over previous
#include <cuda_runtime.h>
#include <cuda_bf16.h>
#include <cstdint>

// ---------------------------------------------------------------------------
// MHA forward: out = (softmax_causal(QK^T/sqrt(D)) V) Wo^T,  also emit attn.
// B=4, L=2048, E=1024, H=16, D=64.
// d_out layout: [out: B*L*E floats][attn: B*H*L*L floats]
// R9: all GEMMs + attention on mma.sync m16n8k16 BF16 with 3xBF16 hi/lo
// compensation (~1e-4 accuracy). Halves mma instruction count vs 3xTF32
// m16n8k8 (R8) -- we are mma-rt bound (tensor=49.5%, issue=26%).
// Operands pre-split ONCE into packed bf16x2 hi/lo smem.
// ---------------------------------------------------------------------------

constexpr int B_ = 4, L_ = 2048, E_ = 1024, H_ = 16, D_ = 64;
constexpr int BH   = B_ * H_;     // 64
constexpr int NTOK = B_ * L_;     // 8192

// Scratch (static __device__ arrays: allocation-free)
__device__ float g_Q[BH * L_ * D_];
__device__ float g_K[BH * L_ * D_];
__device__ float g_V[BH * L_ * D_];
__device__ float g_Oh[BH * L_ * D_];

// ---------------------------------------------------------------------------
// bf16 pack/split helpers
// ---------------------------------------------------------------------------
__device__ __forceinline__ uint32_t pack2(float x0, float x1) {
    // low half = bf16(x0) (element k), high half = bf16(x1) (element k+1)
    uint32_t r;
    asm("cvt.rn.bf16x2.f32 %0, %1, %2;" : "=r"(r) : "f"(x1), "f"(x0));
    return r;
}
// split pair (x0,x1) into packed hi word + packed lo (residual) word
__device__ __forceinline__ void split_pack(float x0, float x1,
                                           uint32_t& h, uint32_t& l) {
    h = pack2(x0, x1);
    float h0 = __uint_as_float(h << 16);
    float h1 = __uint_as_float(h & 0xffff0000u);
    l = pack2(x0 - h0, x1 - h1);
}
__device__ __forceinline__ void mma_bf16(float* c, const uint32_t* a,
                                         const uint32_t* b) {
    asm volatile(
        "mma.sync.aligned.m16n8k16.row.col.f32.bf16.bf16.f32 "
        "{%0,%1,%2,%3}, {%4,%5,%6,%7}, {%8,%9}, {%0,%1,%2,%3};"
        : "+f"(c[0]), "+f"(c[1]), "+f"(c[2]), "+f"(c[3])
        : "r"(a[0]), "r"(a[1]), "r"(a[2]), "r"(a[3]), "r"(b[0]), "r"(b[1]));
}

// ---------------------------------------------------------------------------
// 3xBF16 tensor-core GEMM body (CTA 128x128, BK=16 = one k16 chunk,
// 8 warps of 64x32). C[m,n] = sum_k A[m,k] * B[n,k].
// Packed smem layout [row][k2], stride 12 -> frag LDS banks 12*gr+tig:
// all 32 distinct (conflict-free).
// ---------------------------------------------------------------------------
constexpr int BK = 16;
constexpr int PSTR = 12;          // 8 packed words + 4 pad

struct GemmSmem {
    uint32_t Ah[128][PSTR];
    uint32_t Al[128][PSTR];
    uint32_t Bh[128][PSTR];
    uint32_t Bl[128][PSTR];
};

template <typename FA, typename FB>
__device__ __forceinline__ void load_chunk(GemmSmem& s, int tid, FA getA, FB getB) {
    const int row = tid >> 1;
    const int kq  = (tid & 1) * 8;      // float offset
    const int w0  = (tid & 1) * 4;      // packed word offset
    float4 a0 = *(const float4*)getA(row, kq);
    float4 a1 = *(const float4*)getA(row, kq + 4);
    float4 b0 = *(const float4*)getB(row, kq);
    float4 b1 = *(const float4*)getB(row, kq + 4);
    uint32_t h, l;
    split_pack(a0.x, a0.y, h, l); s.Ah[row][w0 + 0] = h; s.Al[row][w0 + 0] = l;
    split_pack(a0.z, a0.w, h, l); s.Ah[row][w0 + 1] = h; s.Al[row][w0 + 1] = l;
    split_pack(a1.x, a1.y, h, l); s.Ah[row][w0 + 2] = h; s.Al[row][w0 + 2] = l;
    split_pack(a1.z, a1.w, h, l); s.Ah[row][w0 + 3] = h; s.Al[row][w0 + 3] = l;
    split_pack(b0.x, b0.y, h, l); s.Bh[row][w0 + 0] = h; s.Bl[row][w0 + 0] = l;
    split_pack(b0.z, b0.w, h, l); s.Bh[row][w0 + 1] = h; s.Bl[row][w0 + 1] = l;
    split_pack(b1.x, b1.y, h, l); s.Bh[row][w0 + 2] = h; s.Bl[row][w0 + 2] = l;
    split_pack(b1.z, b1.w, h, l); s.Bh[row][w0 + 3] = h; s.Bl[row][w0 + 3] = l;
}

__device__ __forceinline__ void mma_chunk(const GemmSmem& s, int wm, int wn,
                                          int gr, int tig, float acc[4][4][4]) {
    uint32_t ah[4][4], al[4][4];
#pragma unroll
    for (int i = 0; i < 4; i++) {
        const int r = wm + 16 * i + gr;
        ah[i][0] = s.Ah[r][tig];     ah[i][1] = s.Ah[r + 8][tig];
        ah[i][2] = s.Ah[r][tig + 4]; ah[i][3] = s.Ah[r + 8][tig + 4];
        al[i][0] = s.Al[r][tig];     al[i][1] = s.Al[r + 8][tig];
        al[i][2] = s.Al[r][tig + 4]; al[i][3] = s.Al[r + 8][tig + 4];
    }
#pragma unroll
    for (int j = 0; j < 4; j++) {
        const int cn = wn + 8 * j + gr;
        uint32_t bh[2] = {s.Bh[cn][tig], s.Bh[cn][tig + 4]};
        uint32_t bl[2] = {s.Bl[cn][tig], s.Bl[cn][tig + 4]};
#pragma unroll
        for (int i = 0; i < 4; i++) {
            mma_bf16(acc[i][j], ah[i], bh);
            mma_bf16(acc[i][j], ah[i], bl);
            mma_bf16(acc[i][j], al[i], bh);
        }
    }
}

// ---------------------------------------------------------------------------
// Projection GEMM -> per-head layout [B,H,L,D]. blockIdx.z selects q/k/v.
// ---------------------------------------------------------------------------
__global__ __launch_bounds__(256, 2) void proj_tc(
    const float* __restrict__ qin, const float* __restrict__ kin,
    const float* __restrict__ vin,
    const float* __restrict__ Wq, const float* __restrict__ Wk,
    const float* __restrict__ Wv)
{
    const float* X; const float* W; float* Out;
    if (blockIdx.z == 0)      { X = qin; W = Wq; Out = g_Q; }
    else if (blockIdx.z == 1) { X = kin; W = Wk; Out = g_K; }
    else                      { X = vin; W = Wv; Out = g_V; }

    __shared__ GemmSmem s;
    const int tid = threadIdx.x, wid = tid >> 5, lane = tid & 31;
    const int gr = lane >> 2, tig = lane & 3;
    const int wm = (wid & 1) * 64, wn = (wid >> 1) * 32;
    const int m0 = blockIdx.y * 128, n0 = blockIdx.x * 128;

    float acc[4][4][4] = {};
    for (int k0 = 0; k0 < E_; k0 += BK) {
        load_chunk(s, tid,
            [&](int r, int kk) { return &X[(size_t)(m0 + r) * E_ + k0 + kk]; },
            [&](int r, int kk) { return &W[(size_t)(n0 + r) * E_ + k0 + kk]; });
        __syncthreads();
        mma_chunk(s, wm, wn, gr, tig, acc);
        __syncthreads();
    }

#pragma unroll
    for (int i = 0; i < 4; i++) {
        const int m_a = m0 + wm + 16 * i + gr;
        const int m_b = m_a + 8;
        const int ba = m_a >> 11, la = m_a & (L_ - 1);
        const int bb = m_b >> 11, lb = m_b & (L_ - 1);
#pragma unroll
        for (int j = 0; j < 4; j++) {
            const int col = n0 + wn + 8 * j + 2 * tig;
            const int h = col >> 6, d = col & 63;
            *(float2*)&Out[((size_t)(ba * H_ + h) * L_ + la) * D_ + d] =
                make_float2(acc[i][j][0], acc[i][j][1]);
            *(float2*)&Out[((size_t)(bb * H_ + h) * L_ + lb) * D_ + d] =
                make_float2(acc[i][j][2], acc[i][j][3]);
        }
    }
}

// ---------------------------------------------------------------------------
// Output projection: out[m,n] = sum_k Oh[m,k] * Wo[n,k].
// ---------------------------------------------------------------------------
__global__ __launch_bounds__(256, 2) void outproj_tc(
    const float* __restrict__ Wo, float* __restrict__ out)
{
    __shared__ GemmSmem s;
    const int tid = threadIdx.x, wid = tid >> 5, lane = tid & 31;
    const int gr = lane >> 2, tig = lane & 3;
    const int wm = (wid & 1) * 64, wn = (wid >> 1) * 32;
    const int m0 = blockIdx.y * 128, n0 = blockIdx.x * 128;

    float acc[4][4][4] = {};
    for (int k0 = 0; k0 < E_; k0 += BK) {
        load_chunk(s, tid,
            [&](int r, int kk) {
                int m = m0 + r, k = k0 + kk;
                int b = m >> 11, l = m & (L_ - 1);
                return &g_Oh[((size_t)(b * H_ + (k >> 6)) * L_ + l) * D_ + (k & 63)];
            },
            [&](int r, int kk) { return &Wo[(size_t)(n0 + r) * E_ + k0 + kk]; });
        __syncthreads();
        mma_chunk(s, wm, wn, gr, tig, acc);
        __syncthreads();
    }

#pragma unroll
    for (int i = 0; i < 4; i++) {
        const int m_a = m0 + wm + 16 * i + gr;
#pragma unroll
        for (int j = 0; j < 4; j++) {
            const int col = n0 + wn + 8 * j + 2 * tig;
            *(float2*)&out[(size_t)m_a * E_ + col] =
                make_float2(acc[i][j][0], acc[i][j][1]);
            *(float2*)&out[(size_t)(m_a + 8) * E_ + col] =
                make_float2(acc[i][j][2], acc[i][j][3]);
        }
    }
}

// ---------------------------------------------------------------------------
// Tensor-core fused causal attention, 3xBF16, packed pre-split operands.
// CTA = 128 Q-rows; 8 warps (m16 x n64 each); jt-steps of 64 K-columns.
// smem (packed bf16x2, stride 36 -> frag banks 4*gr+tig, conflict-free):
//   KV  [64][36]  hi/lo : K as [key][d2] during QK, V as [col][k2] for PV
//   P2  [128][36] hi/lo : P packed along j, staged by exp phase
// Q pre-split into 32 regs of packed A-frags (no splits in the mainloop).
// ---------------------------------------------------------------------------
__global__ __launch_bounds__(256, 2) void attn_tc(float* __restrict__ attn_base)
{
    extern __shared__ uint32_t usm[];
    uint32_t* KVh = usm;             // 64*36
    uint32_t* KVl = usm + 2304;
    uint32_t* P2h = usm + 4608;      // 128*36
    uint32_t* P2l = usm + 9216;
    float*    sl  = (float*)(usm + 13824);   // 128

    const int bh = blockIdx.y;
    const int it = (int)gridDim.x - 1 - (int)blockIdx.x;   // heavy tiles first
    const int q0 = it * 128;
    const int tid = threadIdx.x, wid = tid >> 5, lane = tid & 31;
    const int gr = lane >> 2, tig = lane & 3;
    const int wm = wid * 16;

    const float* Qp = g_Q + (size_t)bh * L_ * D_;
    const float* Kp = g_K + (size_t)bh * L_ * D_;
    const float* Vp = g_V + (size_t)bh * L_ * D_;
    float* attn = attn_base + (size_t)bh * L_ * L_;

    // Q A-fragments, pre-split packed bf16x2 (4 k16-chunks over D=64)
    uint32_t qh[4][4], ql[4][4];
    const int grow0 = q0 + wm + gr, grow1 = grow0 + 8;
    {
#pragma unroll
        for (int kc = 0; kc < 4; kc++) {
            float2 q00 = *(const float2*)&Qp[(size_t)grow0 * D_ + kc * 16 + 2 * tig];
            float2 q10 = *(const float2*)&Qp[(size_t)grow1 * D_ + kc * 16 + 2 * tig];
            float2 q01 = *(const float2*)&Qp[(size_t)grow0 * D_ + kc * 16 + 2 * tig + 8];
            float2 q11 = *(const float2*)&Qp[(size_t)grow1 * D_ + kc * 16 + 2 * tig + 8];
            split_pack(q00.x, q00.y, qh[kc][0], ql[kc][0]);
            split_pack(q10.x, q10.y, qh[kc][1], ql[kc][1]);
            split_pack(q01.x, q01.y, qh[kc][2], ql[kc][2]);
            split_pack(q11.x, q11.y, qh[kc][3], ql[kc][3]);
        }
    }

    float l0 = 0.f, l1 = 0.f;
    float oa[8][4] = {};
    const int ntiles = 2 * it + 2;
    const float scale = 0.125f;          // 1/sqrt(64)

    for (int jt = 0; jt < ntiles; jt++) {
        __syncthreads();   // prev PV done reading KV(V)/P2
        // K tile -> packed hi/lo smem [key][d2]
#pragma unroll
        for (int c = 0; c < 4; c++) {
            int id = c * 256 + tid;
            int r = id >> 4, d4 = (id & 15) << 2, w = (id & 15) << 1;
            float4 kv = *(const float4*)&Kp[(size_t)(jt * 64 + r) * D_ + d4];
            uint32_t h0, lo0, h1, lo1;
            split_pack(kv.x, kv.y, h0, lo0);
            split_pack(kv.z, kv.w, h1, lo1);
            *(uint2*)&KVh[r * 36 + w] = make_uint2(h0, h1);
            *(uint2*)&KVl[r * 36 + w] = make_uint2(lo0, lo1);
        }
        __syncthreads();

        // S = Q K^T (3xBF16)
        float sc[8][4];
#pragma unroll
        for (int nt = 0; nt < 8; nt++)
            sc[nt][0] = sc[nt][1] = sc[nt][2] = sc[nt][3] = 0.f;
#pragma unroll
        for (int kc = 0; kc < 4; kc++) {
#pragma unroll
            for (int nt = 0; nt < 8; nt++) {
                const int rb = (nt * 8 + gr) * 36 + kc * 8 + tig;
                uint32_t bhv[2] = {KVh[rb], KVh[rb + 4]};
                uint32_t blv[2] = {KVl[rb], KVl[rb + 4]};
                mma_bf16(sc[nt], qh[kc], bhv);
                mma_bf16(sc[nt], qh[kc], blv);
                mma_bf16(sc[nt], ql[kc], bhv);
            }
        }

        // exp + causal mask; accumulate l; stage packed P; write unnorm P
        float pl0 = 0.f, pl1 = 0.f;
#pragma unroll
        for (int nt = 0; nt < 8; nt++) {
            int jc = jt * 64 + nt * 8 + 2 * tig;
            float p0 = __expf(sc[nt][0] * scale); if (jc     > grow0) p0 = 0.f;
            float p1 = __expf(sc[nt][1] * scale); if (jc + 1 > grow0) p1 = 0.f;
            float p2 = __expf(sc[nt][2] * scale); if (jc     > grow1) p2 = 0.f;
            float p3 = __expf(sc[nt][3] * scale); if (jc + 1 > grow1) p3 = 0.f;
            pl0 += p0 + p1;
            pl1 += p2 + p3;
            uint32_t h, l;
            split_pack(p0, p1, h, l);
            P2h[(wm + gr) * 36 + nt * 4 + tig] = h;
            P2l[(wm + gr) * 36 + nt * 4 + tig] = l;
            split_pack(p2, p3, h, l);
            P2h[(wm + gr + 8) * 36 + nt * 4 + tig] = h;
            P2l[(wm + gr + 8) * 36 + nt * 4 + tig] = l;
            *(float2*)&attn[(size_t)grow0 * L_ + jc] = make_float2(p0, p1);
            *(float2*)&attn[(size_t)grow1 * L_ + jc] = make_float2(p2, p3);
        }
        pl0 += __shfl_xor_sync(0xffffffffu, pl0, 1);
        pl0 += __shfl_xor_sync(0xffffffffu, pl0, 2);
        pl1 += __shfl_xor_sync(0xffffffffu, pl1, 1);
        pl1 += __shfl_xor_sync(0xffffffffu, pl1, 2);
        l0 += pl0; l1 += pl1;
        __syncthreads();   // QK reads of KV(K) done; P2 visible

        // V tile -> same buffers, transposed-packed [col][k2]
        // (word at [c][k2] packs V[2*k2][c] low, V[2*k2+1][c] high)
#pragma unroll
        for (int c = 0; c < 2; c++) {
            int rp = (tid & 15) + c * 16;     // row pair 0..31
            int d0 = (tid >> 4) * 4;          // col 0..60
            float4 v0 = *(const float4*)&Vp[(size_t)(jt * 64 + 2 * rp) * D_ + d0];
            float4 v1 = *(const float4*)&Vp[(size_t)(jt * 64 + 2 * rp + 1) * D_ + d0];
            uint32_t h, l;
            split_pack(v0.x, v1.x, h, l); KVh[(d0 + 0) * 36 + rp] = h; KVl[(d0 + 0) * 36 + rp] = l;
            split_pack(v0.y, v1.y, h, l); KVh[(d0 + 1) * 36 + rp] = h; KVl[(d0 + 1) * 36 + rp] = l;
            split_pack(v0.z, v1.z, h, l); KVh[(d0 + 2) * 36 + rp] = h; KVl[(d0 + 2) * 36 + rp] = l;
            split_pack(v0.w, v1.w, h, l); KVh[(d0 + 3) * 36 + rp] = h; KVl[(d0 + 3) * 36 + rp] = l;
        }
        __syncthreads();

        // O += P V (3xBF16)
#pragma unroll
        for (int kc = 0; kc < 4; kc++) {
            const int a0 = (wm + gr) * 36 + kc * 8 + tig;
            const int a1 = (wm + gr + 8) * 36 + kc * 8 + tig;
            uint32_t ph[4]  = {P2h[a0], P2h[a1], P2h[a0 + 4], P2h[a1 + 4]};
            uint32_t plo[4] = {P2l[a0], P2l[a1], P2l[a0 + 4], P2l[a1 + 4]};
#pragma unroll
            for (int nt = 0; nt < 8; nt++) {
                const int vb = (nt * 8 + gr) * 36 + kc * 8 + tig;
                uint32_t bhv[2] = {KVh[vb], KVh[vb + 4]};
                uint32_t blv[2] = {KVl[vb], KVl[vb + 4]};
                mma_bf16(oa[nt], ph, bhv);
                mma_bf16(oa[nt], ph, blv);
                mma_bf16(oa[nt], plo, bhv);
            }
        }
    }

    const float inv0 = 1.f / l0, inv1 = 1.f / l1;
    if (tig == 0) {
        sl[wm + gr] = inv0;
        sl[wm + gr + 8] = inv1;
    }
    // normalized O -> scratch [B,H,L,D]
#pragma unroll
    for (int nt = 0; nt < 8; nt++) {
        *(float2*)&g_Oh[((size_t)bh * L_ + grow0) * D_ + nt * 8 + 2 * tig] =
            make_float2(oa[nt][0] * inv0, oa[nt][1] * inv0);
        *(float2*)&g_Oh[((size_t)bh * L_ + grow1) * D_ + nt * 8 + 2 * tig] =
            make_float2(oa[nt][2] * inv1, oa[nt][3] * inv1);
    }
    __syncthreads();   // sl visible; all P gmem writes done CTA-wide

    // normalize lower tiles in place; zero-fill upper triangle
    for (int j2 = 0; j2 < ntiles; j2++) {
#pragma unroll
        for (int c = 0; c < 8; c++) {
            int id = c * 256 + tid;
            int r = id >> 4, c4 = (id & 15) << 2;
            float inv = sl[r];
            float* p = &attn[(size_t)(q0 + r) * L_ + j2 * 64 + c4];
            float4 v = *(float4*)p;
            v.x *= inv; v.y *= inv; v.z *= inv; v.w *= inv;
            *(float4*)p = v;
        }
    }
    const float4 z4 = make_float4(0.f, 0.f, 0.f, 0.f);
    for (int j2 = ntiles; j2 < L_ / 64; j2++) {
#pragma unroll
        for (int c = 0; c < 8; c++) {
            int id = c * 256 + tid;
            int r = id >> 4, c4 = (id & 15) << 2;
            *(float4*)&attn[(size_t)(q0 + r) * L_ + j2 * 64 + c4] = z4;
        }
    }
}

constexpr int ATTN_SMEM = (13824 + 128) * 4 + 256;   // ~56KB dynamic

// ---------------------------------------------------------------------------
extern "C" void kernel_launch(void* const* d_in, const int* in_sizes, int n_in,
                              void* d_out, int out_size)
{
    const float* qkv[3] = {nullptr, nullptr, nullptr};
    const float* Ws[4]  = {nullptr, nullptr, nullptr, nullptr};
    int nqkv = 0, nw = 0;
    for (int i = 0; i < n_in; i++) {
        if (in_sizes[i] == NTOK * E_) { if (nqkv < 3) qkv[nqkv++] = (const float*)d_in[i]; }
        else if (in_sizes[i] == E_ * E_) { if (nw < 4) Ws[nw++] = (const float*)d_in[i]; }
    }
    const float* q  = qkv[0]; const float* k  = qkv[1]; const float* v  = qkv[2];
    const float* Wq = Ws[0];  const float* Wk = Ws[1];
    const float* Wv = Ws[2];  const float* Wo = Ws[3];

    float* out  = (float*)d_out;
    float* attn = out + (size_t)B_ * L_ * E_;

    cudaFuncSetAttribute(attn_tc, cudaFuncAttributeMaxDynamicSharedMemorySize,
                         ATTN_SMEM);

    proj_tc<<<dim3(E_ / 128, NTOK / 128, 3), 256>>>(q, k, v, Wq, Wk, Wv);
    attn_tc<<<dim3(L_ / 128, BH), 256, ATTN_SMEM>>>(attn);
    outproj_tc<<<dim3(E_ / 128, NTOK / 128), 256>>>(Wo, out);
}

// round 10
// speedup vs baseline: 1.8245x; 1.0466x over previous
#include <cuda_runtime.h>
#include <cuda_bf16.h>
#include <cstdint>

// ---------------------------------------------------------------------------
// MHA forward: out = (softmax_causal(QK^T/sqrt(D)) V) Wo^T,  also emit attn.
// B=4, L=2048, E=1024, H=16, D=64.
// d_out layout: [out: B*L*E floats][attn: B*H*L*L floats]
// 3xBF16 m16n8k16 everywhere. R10: ping-pong double-buffered GEMMs and
// prefetched attention tiles (R9 was latency-exposed: tensor 39%, issue 20%).
// ---------------------------------------------------------------------------

constexpr int B_ = 4, L_ = 2048, E_ = 1024, H_ = 16, D_ = 64;
constexpr int BH   = B_ * H_;     // 64
constexpr int NTOK = B_ * L_;     // 8192

__device__ float g_Q[BH * L_ * D_];
__device__ float g_K[BH * L_ * D_];
__device__ float g_V[BH * L_ * D_];
__device__ float g_Oh[BH * L_ * D_];

// ---------------------------------------------------------------------------
__device__ __forceinline__ uint32_t pack2(float x0, float x1) {
    uint32_t r;
    asm("cvt.rn.bf16x2.f32 %0, %1, %2;" : "=r"(r) : "f"(x1), "f"(x0));
    return r;
}
__device__ __forceinline__ void split_pack(float x0, float x1,
                                           uint32_t& h, uint32_t& l) {
    h = pack2(x0, x1);
    float h0 = __uint_as_float(h << 16);
    float h1 = __uint_as_float(h & 0xffff0000u);
    l = pack2(x0 - h0, x1 - h1);
}
__device__ __forceinline__ void mma_bf16(float* c, const uint32_t* a,
                                         const uint32_t* b) {
    asm volatile(
        "mma.sync.aligned.m16n8k16.row.col.f32.bf16.bf16.f32 "
        "{%0,%1,%2,%3}, {%4,%5,%6,%7}, {%8,%9}, {%0,%1,%2,%3};"
        : "+f"(c[0]), "+f"(c[1]), "+f"(c[2]), "+f"(c[3])
        : "r"(a[0]), "r"(a[1]), "r"(a[2]), "r"(a[3]), "r"(b[0]), "r"(b[1]));
}

constexpr int BK = 16;
constexpr int NKC = E_ / BK;      // 64 chunks
constexpr int PSTR = 12;          // 8 packed words + 4 pad (conflict-free)

// ---------------------------------------------------------------------------
// 3xBF16 GEMM body (CTA 128x128, k16 chunks, 8 warps of 64x32), ping-pong.
// ---------------------------------------------------------------------------
struct GemmSmem {
    uint32_t Ah[128][PSTR];
    uint32_t Al[128][PSTR];
    uint32_t Bh[128][PSTR];
    uint32_t Bl[128][PSTR];
};
constexpr int GEMM_SMEM = 2 * (int)sizeof(GemmSmem);   // 49152

template <typename FA, typename FB>
__device__ __forceinline__ void ldg_chunk(int tid, FA getA, FB getB, float4 r[4]) {
    const int row = tid >> 1;
    const int kq  = (tid & 1) * 8;
    r[0] = *(const float4*)getA(row, kq);
    r[1] = *(const float4*)getA(row, kq + 4);
    r[2] = *(const float4*)getB(row, kq);
    r[3] = *(const float4*)getB(row, kq + 4);
}
__device__ __forceinline__ void sts_chunk(GemmSmem& s, int tid, const float4 r[4]) {
    const int row = tid >> 1;
    const int w0  = (tid & 1) * 4;
    uint32_t h, l;
    split_pack(r[0].x, r[0].y, h, l); s.Ah[row][w0 + 0] = h; s.Al[row][w0 + 0] = l;
    split_pack(r[0].z, r[0].w, h, l); s.Ah[row][w0 + 1] = h; s.Al[row][w0 + 1] = l;
    split_pack(r[1].x, r[1].y, h, l); s.Ah[row][w0 + 2] = h; s.Al[row][w0 + 2] = l;
    split_pack(r[1].z, r[1].w, h, l); s.Ah[row][w0 + 3] = h; s.Al[row][w0 + 3] = l;
    split_pack(r[2].x, r[2].y, h, l); s.Bh[row][w0 + 0] = h; s.Bl[row][w0 + 0] = l;
    split_pack(r[2].z, r[2].w, h, l); s.Bh[row][w0 + 1] = h; s.Bl[row][w0 + 1] = l;
    split_pack(r[3].x, r[3].y, h, l); s.Bh[row][w0 + 2] = h; s.Bl[row][w0 + 2] = l;
    split_pack(r[3].z, r[3].w, h, l); s.Bh[row][w0 + 3] = h; s.Bl[row][w0 + 3] = l;
}

__device__ __forceinline__ void mma_chunk(const GemmSmem& s, int wm, int wn,
                                          int gr, int tig, float acc[4][4][4]) {
    uint32_t ah[4][4], al[4][4];
#pragma unroll
    for (int i = 0; i < 4; i++) {
        const int r = wm + 16 * i + gr;
        ah[i][0] = s.Ah[r][tig];     ah[i][1] = s.Ah[r + 8][tig];
        ah[i][2] = s.Ah[r][tig + 4]; ah[i][3] = s.Ah[r + 8][tig + 4];
        al[i][0] = s.Al[r][tig];     al[i][1] = s.Al[r + 8][tig];
        al[i][2] = s.Al[r][tig + 4]; al[i][3] = s.Al[r + 8][tig + 4];
    }
#pragma unroll
    for (int j = 0; j < 4; j++) {
        const int cn = wn + 8 * j + gr;
        uint32_t bh[2] = {s.Bh[cn][tig], s.Bh[cn][tig + 4]};
        uint32_t bl[2] = {s.Bl[cn][tig], s.Bl[cn][tig + 4]};
#pragma unroll
        for (int i = 0; i < 4; i++) {
            mma_bf16(acc[i][j], ah[i], bh);
            mma_bf16(acc[i][j], ah[i], bl);
            mma_bf16(acc[i][j], al[i], bh);
        }
    }
}

// ---------------------------------------------------------------------------
// Projection GEMM -> per-head layout [B,H,L,D]. blockIdx.z selects q/k/v.
// ---------------------------------------------------------------------------
__global__ __launch_bounds__(256, 2) void proj_tc(
    const float* __restrict__ qin, const float* __restrict__ kin,
    const float* __restrict__ vin,
    const float* __restrict__ Wq, const float* __restrict__ Wk,
    const float* __restrict__ Wv)
{
    const float* X; const float* W; float* Out;
    if (blockIdx.z == 0)      { X = qin; W = Wq; Out = g_Q; }
    else if (blockIdx.z == 1) { X = kin; W = Wk; Out = g_K; }
    else                      { X = vin; W = Wv; Out = g_V; }

    extern __shared__ GemmSmem gsm[];
    const int tid = threadIdx.x, wid = tid >> 5, lane = tid & 31;
    const int gr = lane >> 2, tig = lane & 3;
    const int wm = (wid & 1) * 64, wn = (wid >> 1) * 32;
    const int m0 = blockIdx.y * 128, n0 = blockIdx.x * 128;

    auto getA = [&](int k0) {
        return [=](int r, int kk) { return &X[(size_t)(m0 + r) * E_ + k0 + kk]; };
    };
    auto getB = [&](int k0) {
        return [=](int r, int kk) { return &W[(size_t)(n0 + r) * E_ + k0 + kk]; };
    };

    float4 pre[4];
    ldg_chunk(tid, getA(0), getB(0), pre);
    sts_chunk(gsm[0], tid, pre);
    __syncthreads();

    float acc[4][4][4] = {};
    for (int kc = 0; kc < NKC; kc++) {
        if (kc + 1 < NKC)
            ldg_chunk(tid, getA((kc + 1) * BK), getB((kc + 1) * BK), pre);
        mma_chunk(gsm[kc & 1], wm, wn, gr, tig, acc);
        if (kc + 1 < NKC)
            sts_chunk(gsm[(kc + 1) & 1], tid, pre);
        __syncthreads();
    }

#pragma unroll
    for (int i = 0; i < 4; i++) {
        const int m_a = m0 + wm + 16 * i + gr;
        const int m_b = m_a + 8;
        const int ba = m_a >> 11, la = m_a & (L_ - 1);
        const int bb = m_b >> 11, lb = m_b & (L_ - 1);
#pragma unroll
        for (int j = 0; j < 4; j++) {
            const int col = n0 + wn + 8 * j + 2 * tig;
            const int h = col >> 6, d = col & 63;
            *(float2*)&Out[((size_t)(ba * H_ + h) * L_ + la) * D_ + d] =
                make_float2(acc[i][j][0], acc[i][j][1]);
            *(float2*)&Out[((size_t)(bb * H_ + h) * L_ + lb) * D_ + d] =
                make_float2(acc[i][j][2], acc[i][j][3]);
        }
    }
}

// ---------------------------------------------------------------------------
// Output projection: out[m,n] = sum_k Oh[m,k] * Wo[n,k].
// ---------------------------------------------------------------------------
__global__ __launch_bounds__(256, 2) void outproj_tc(
    const float* __restrict__ Wo, float* __restrict__ out)
{
    extern __shared__ GemmSmem gsm[];
    const int tid = threadIdx.x, wid = tid >> 5, lane = tid & 31;
    const int gr = lane >> 2, tig = lane & 3;
    const int wm = (wid & 1) * 64, wn = (wid >> 1) * 32;
    const int m0 = blockIdx.y * 128, n0 = blockIdx.x * 128;

    auto getA = [&](int k0) {
        return [=](int r, int kk) {
            int m = m0 + r, k = k0 + kk;
            int b = m >> 11, l = m & (L_ - 1);
            return &g_Oh[((size_t)(b * H_ + (k >> 6)) * L_ + l) * D_ + (k & 63)];
        };
    };
    auto getB = [&](int k0) {
        return [=](int r, int kk) { return &Wo[(size_t)(n0 + r) * E_ + k0 + kk]; };
    };

    float4 pre[4];
    ldg_chunk(tid, getA(0), getB(0), pre);
    sts_chunk(gsm[0], tid, pre);
    __syncthreads();

    float acc[4][4][4] = {};
    for (int kc = 0; kc < NKC; kc++) {
        if (kc + 1 < NKC)
            ldg_chunk(tid, getA((kc + 1) * BK), getB((kc + 1) * BK), pre);
        mma_chunk(gsm[kc & 1], wm, wn, gr, tig, acc);
        if (kc + 1 < NKC)
            sts_chunk(gsm[(kc + 1) & 1], tid, pre);
        __syncthreads();
    }

#pragma unroll
    for (int i = 0; i < 4; i++) {
        const int m_a = m0 + wm + 16 * i + gr;
#pragma unroll
        for (int j = 0; j < 4; j++) {
            const int col = n0 + wn + 8 * j + 2 * tig;
            *(float2*)&out[(size_t)m_a * E_ + col] =
                make_float2(acc[i][j][0], acc[i][j][1]);
            *(float2*)&out[(size_t)(m_a + 8) * E_ + col] =
                make_float2(acc[i][j][2], acc[i][j][3]);
        }
    }
}

// ---------------------------------------------------------------------------
// Tensor-core fused causal attention, 3xBF16, prefetched tiles.
// CTA = 128 Q-rows; 8 warps (m16 x n64); jt-steps of 64 K-columns.
// Loop: sync -> STS K&V (from prefetch regs) -> sync -> LDG(jt+1) ->
//       QK+exp (nt-pairs, fused) -> syncwarp -> PV.
// smem: Kh/Kl, Vh/Vl [64][36], P2h/P2l [128][36], sl[128]  (~72.5KB, 2 CTA/SM)
// ---------------------------------------------------------------------------
__global__ __launch_bounds__(256, 2) void attn_tc(float* __restrict__ attn_base)
{
    extern __shared__ uint32_t usm[];
    uint32_t* Kh  = usm;               // 64*36 = 2304
    uint32_t* Kl  = usm + 2304;
    uint32_t* Vh  = usm + 4608;
    uint32_t* Vl  = usm + 6912;
    uint32_t* P2h = usm + 9216;        // 128*36 = 4608
    uint32_t* P2l = usm + 13824;
    float*    sl  = (float*)(usm + 18432);   // 128

    const int bh = blockIdx.y;
    const int it = (int)gridDim.x - 1 - (int)blockIdx.x;   // heavy tiles first
    const int q0 = it * 128;
    const int tid = threadIdx.x, wid = tid >> 5, lane = tid & 31;
    const int gr = lane >> 2, tig = lane & 3;
    const int wm = wid * 16;

    const float* Qp = g_Q + (size_t)bh * L_ * D_;
    const float* Kp = g_K + (size_t)bh * L_ * D_;
    const float* Vp = g_V + (size_t)bh * L_ * D_;
    float* attn = attn_base + (size_t)bh * L_ * L_;

    // Q A-fragments, pre-split packed bf16x2 (4 k16-chunks over D=64)
    uint32_t qh[4][4], ql[4][4];
    const int grow0 = q0 + wm + gr, grow1 = grow0 + 8;
#pragma unroll
    for (int kc = 0; kc < 4; kc++) {
        float2 q00 = *(const float2*)&Qp[(size_t)grow0 * D_ + kc * 16 + 2 * tig];
        float2 q10 = *(const float2*)&Qp[(size_t)grow1 * D_ + kc * 16 + 2 * tig];
        float2 q01 = *(const float2*)&Qp[(size_t)grow0 * D_ + kc * 16 + 2 * tig + 8];
        float2 q11 = *(const float2*)&Qp[(size_t)grow1 * D_ + kc * 16 + 2 * tig + 8];
        split_pack(q00.x, q00.y, qh[kc][0], ql[kc][0]);
        split_pack(q10.x, q10.y, qh[kc][1], ql[kc][1]);
        split_pack(q01.x, q01.y, qh[kc][2], ql[kc][2]);
        split_pack(q11.x, q11.y, qh[kc][3], ql[kc][3]);
    }

    const int ntiles = 2 * it + 2;
    const float scale = 0.125f;          // 1/sqrt(64)

    // prefetch registers for K (natural) and V (transposed pair) tiles
    float4 kpre[4], vpre[4];
    auto prefetch = [&](int jt) {
#pragma unroll
        for (int c = 0; c < 4; c++) {
            int id = c * 256 + tid;
            int r = id >> 4, d4 = (id & 15) << 2;
            kpre[c] = *(const float4*)&Kp[(size_t)(jt * 64 + r) * D_ + d4];
        }
#pragma unroll
        for (int c = 0; c < 2; c++) {
            int rp = (tid & 15) + c * 16;
            int d0 = (tid >> 4) * 4;
            vpre[2 * c]     = *(const float4*)&Vp[(size_t)(jt * 64 + 2 * rp) * D_ + d0];
            vpre[2 * c + 1] = *(const float4*)&Vp[(size_t)(jt * 64 + 2 * rp + 1) * D_ + d0];
        }
    };
    prefetch(0);

    float l0 = 0.f, l1 = 0.f;            // lane-partial row sums
    float oa[8][4] = {};

    for (int jt = 0; jt < ntiles; jt++) {
        __syncthreads();   // prior consumers done with K/V buffers
        // STS K [key][d2]
#pragma unroll
        for (int c = 0; c < 4; c++) {
            int id = c * 256 + tid;
            int r = id >> 4, w = (id & 15) << 1;
            uint32_t h0, lo0, h1, lo1;
            split_pack(kpre[c].x, kpre[c].y, h0, lo0);
            split_pack(kpre[c].z, kpre[c].w, h1, lo1);
            *(uint2*)&Kh[r * 36 + w] = make_uint2(h0, h1);
            *(uint2*)&Kl[r * 36 + w] = make_uint2(lo0, lo1);
        }
        // STS V transposed-packed [col][k2]
#pragma unroll
        for (int c = 0; c < 2; c++) {
            int rp = (tid & 15) + c * 16;
            int d0 = (tid >> 4) * 4;
            float4 v0 = vpre[2 * c], v1 = vpre[2 * c + 1];
            uint32_t h, l;
            split_pack(v0.x, v1.x, h, l); Vh[(d0 + 0) * 36 + rp] = h; Vl[(d0 + 0) * 36 + rp] = l;
            split_pack(v0.y, v1.y, h, l); Vh[(d0 + 1) * 36 + rp] = h; Vl[(d0 + 1) * 36 + rp] = l;
            split_pack(v0.z, v1.z, h, l); Vh[(d0 + 2) * 36 + rp] = h; Vl[(d0 + 2) * 36 + rp] = l;
            split_pack(v0.w, v1.w, h, l); Vh[(d0 + 3) * 36 + rp] = h; Vl[(d0 + 3) * 36 + rp] = l;
        }
        __syncthreads();
        if (jt + 1 < ntiles) prefetch(jt + 1);   // hidden by QK/exp/PV below

        // QK + exp fused, nt-pairs (keeps sc live range at 8 regs)
#pragma unroll
        for (int np = 0; np < 4; np++) {
            float sc[2][4] = {};
#pragma unroll
            for (int kc = 0; kc < 4; kc++) {
#pragma unroll
                for (int u = 0; u < 2; u++) {
                    const int nt = 2 * np + u;
                    const int rb = (nt * 8 + gr) * 36 + kc * 8 + tig;
                    uint32_t bhv[2] = {Kh[rb], Kh[rb + 4]};
                    uint32_t blv[2] = {Kl[rb], Kl[rb + 4]};
                    mma_bf16(sc[u], qh[kc], bhv);
                    mma_bf16(sc[u], qh[kc], blv);
                    mma_bf16(sc[u], ql[kc], bhv);
                }
            }
#pragma unroll
            for (int u = 0; u < 2; u++) {
                const int nt = 2 * np + u;
                int jc = jt * 64 + nt * 8 + 2 * tig;
                float p0 = __expf(sc[u][0] * scale); if (jc     > grow0) p0 = 0.f;
                float p1 = __expf(sc[u][1] * scale); if (jc + 1 > grow0) p1 = 0.f;
                float p2 = __expf(sc[u][2] * scale); if (jc     > grow1) p2 = 0.f;
                float p3 = __expf(sc[u][3] * scale); if (jc + 1 > grow1) p3 = 0.f;
                l0 += p0 + p1;
                l1 += p2 + p3;
                uint32_t h, l;
                split_pack(p0, p1, h, l);
                P2h[(wm + gr) * 36 + nt * 4 + tig] = h;
                P2l[(wm + gr) * 36 + nt * 4 + tig] = l;
                split_pack(p2, p3, h, l);
                P2h[(wm + gr + 8) * 36 + nt * 4 + tig] = h;
                P2l[(wm + gr + 8) * 36 + nt * 4 + tig] = l;
                *(float2*)&attn[(size_t)grow0 * L_ + jc] = make_float2(p0, p1);
                *(float2*)&attn[(size_t)grow1 * L_ + jc] = make_float2(p2, p3);
            }
        }
        __syncwarp();   // P2 rows are warp-private: warp fence suffices

        // O += P V (3xBF16)
#pragma unroll
        for (int kc = 0; kc < 4; kc++) {
            const int a0 = (wm + gr) * 36 + kc * 8 + tig;
            const int a1 = (wm + gr + 8) * 36 + kc * 8 + tig;
            uint32_t ph[4]  = {P2h[a0], P2h[a1], P2h[a0 + 4], P2h[a1 + 4]};
            uint32_t plo[4] = {P2l[a0], P2l[a1], P2l[a0 + 4], P2l[a1 + 4]};
#pragma unroll
            for (int nt = 0; nt < 8; nt++) {
                const int vb = (nt * 8 + gr) * 36 + kc * 8 + tig;
                uint32_t bhv[2] = {Vh[vb], Vh[vb + 4]};
                uint32_t blv[2] = {Vl[vb], Vl[vb + 4]};
                mma_bf16(oa[nt], ph, bhv);
                mma_bf16(oa[nt], ph, blv);
                mma_bf16(oa[nt], plo, bhv);
            }
        }
    }

    // row sums: reduce lane partials over the quad (tig)
    l0 += __shfl_xor_sync(0xffffffffu, l0, 1);
    l0 += __shfl_xor_sync(0xffffffffu, l0, 2);
    l1 += __shfl_xor_sync(0xffffffffu, l1, 1);
    l1 += __shfl_xor_sync(0xffffffffu, l1, 2);
    const float inv0 = 1.f / l0, inv1 = 1.f / l1;
    if (tig == 0) {
        sl[wm + gr] = inv0;
        sl[wm + gr + 8] = inv1;
    }
    // normalized O -> scratch [B,H,L,D]
#pragma unroll
    for (int nt = 0; nt < 8; nt++) {
        *(float2*)&g_Oh[((size_t)bh * L_ + grow0) * D_ + nt * 8 + 2 * tig] =
            make_float2(oa[nt][0] * inv0, oa[nt][1] * inv0);
        *(float2*)&g_Oh[((size_t)bh * L_ + grow1) * D_ + nt * 8 + 2 * tig] =
            make_float2(oa[nt][2] * inv1, oa[nt][3] * inv1);
    }
    __syncthreads();   // sl visible; all P gmem writes done CTA-wide

    // normalize lower tiles in place (L2-hot); zero-fill upper triangle
    for (int j2 = 0; j2 < ntiles; j2++) {
#pragma unroll
        for (int c = 0; c < 8; c++) {
            int id = c * 256 + tid;
            int r = id >> 4, c4 = (id & 15) << 2;
            float inv = sl[r];
            float* p = &attn[(size_t)(q0 + r) * L_ + j2 * 64 + c4];
            float4 v = *(float4*)p;
            v.x *= inv; v.y *= inv; v.z *= inv; v.w *= inv;
            *(float4*)p = v;
        }
    }
    const float4 z4 = make_float4(0.f, 0.f, 0.f, 0.f);
    for (int j2 = ntiles; j2 < L_ / 64; j2++) {
#pragma unroll
        for (int c = 0; c < 8; c++) {
            int id = c * 256 + tid;
            int r = id >> 4, c4 = (id & 15) << 2;
            *(float4*)&attn[(size_t)(q0 + r) * L_ + j2 * 64 + c4] = z4;
        }
    }
}

constexpr int ATTN_SMEM = (18432 + 128) * 4 + 256;   // ~74.5KB dynamic

// ---------------------------------------------------------------------------
extern "C" void kernel_launch(void* const* d_in, const int* in_sizes, int n_in,
                              void* d_out, int out_size)
{
    const float* qkv[3] = {nullptr, nullptr, nullptr};
    const float* Ws[4]  = {nullptr, nullptr, nullptr, nullptr};
    int nqkv = 0, nw = 0;
    for (int i = 0; i < n_in; i++) {
        if (in_sizes[i] == NTOK * E_) { if (nqkv < 3) qkv[nqkv++] = (const float*)d_in[i]; }
        else if (in_sizes[i] == E_ * E_) { if (nw < 4) Ws[nw++] = (const float*)d_in[i]; }
    }
    const float* q  = qkv[0]; const float* k  = qkv[1]; const float* v  = qkv[2];
    const float* Wq = Ws[0];  const float* Wk = Ws[1];
    const float* Wv = Ws[2];  const float* Wo = Ws[3];

    float* out  = (float*)d_out;
    float* attn = out + (size_t)B_ * L_ * E_;

    cudaFuncSetAttribute(proj_tc, cudaFuncAttributeMaxDynamicSharedMemorySize, GEMM_SMEM);
    cudaFuncSetAttribute(outproj_tc, cudaFuncAttributeMaxDynamicSharedMemorySize, GEMM_SMEM);
    cudaFuncSetAttribute(attn_tc, cudaFuncAttributeMaxDynamicSharedMemorySize, ATTN_SMEM);

    proj_tc<<<dim3(E_ / 128, NTOK / 128, 3), 256, GEMM_SMEM>>>(q, k, v, Wq, Wk, Wv);
    attn_tc<<<dim3(L_ / 128, BH), 256, ATTN_SMEM>>>(attn);
    outproj_tc<<<dim3(E_ / 128, NTOK / 128), 256, GEMM_SMEM>>>(Wo, out);
}

// round 11
// speedup vs baseline: 1.9042x; 1.0436x over previous
#include <cuda_runtime.h>
#include <cstdint>

// ---------------------------------------------------------------------------
// MHA forward: out = (softmax_causal(QK^T/sqrt(D)) V) Wo^T,  also emit attn.
// B=4, L=2048, E=1024, H=16, D=64.
// d_out layout: [out: B*L*E floats][attn: B*H*L*L floats]
// 3xBF16 m16n8k16 everywhere. R11: operands pre-packed into bf16 hi/lo
// global arrays by prep kernels; GEMMs are cp.async 3-stage pipelines;
// attention K/V tiles cp.async double-buffered. No split work in hot loops
// except P (computed in-kernel).
// ---------------------------------------------------------------------------

constexpr int B_ = 4, L_ = 2048, E_ = 1024, H_ = 16, D_ = 64;
constexpr int BH   = B_ * H_;     // 64
constexpr int NTOK = B_ * L_;     // 8192

// fp32 scratch
__device__ float g_Q[BH * L_ * D_];
__device__ float g_V[BH * L_ * D_];
// packed bf16 hi/lo operands
__device__ uint32_t g_inh[3 * NTOK * E_ / 2], g_inl[3 * NTOK * E_ / 2];
__device__ uint32_t g_Wh[4 * E_ * E_ / 2],   g_Wl[4 * E_ * E_ / 2];
__device__ uint32_t g_Khg[BH * L_ * D_ / 2], g_Klg[BH * L_ * D_ / 2];
__device__ uint32_t g_Vph[BH * D_ * L_ / 2], g_Vpl[BH * D_ * L_ / 2];
__device__ uint32_t g_Ohh[BH * L_ * D_ / 2], g_Ohl[BH * L_ * D_ / 2];

// ---------------------------------------------------------------------------
__device__ __forceinline__ uint32_t pack2(float x0, float x1) {
    uint32_t r;
    asm("cvt.rn.bf16x2.f32 %0, %1, %2;" : "=r"(r) : "f"(x1), "f"(x0));
    return r;
}
__device__ __forceinline__ void split_pack(float x0, float x1,
                                           uint32_t& h, uint32_t& l) {
    h = pack2(x0, x1);
    float h0 = __uint_as_float(h << 16);
    float h1 = __uint_as_float(h & 0xffff0000u);
    l = pack2(x0 - h0, x1 - h1);
}
__device__ __forceinline__ void mma_bf16(float* c, const uint32_t* a,
                                         const uint32_t* b) {
    asm volatile(
        "mma.sync.aligned.m16n8k16.row.col.f32.bf16.bf16.f32 "
        "{%0,%1,%2,%3}, {%4,%5,%6,%7}, {%8,%9}, {%0,%1,%2,%3};"
        : "+f"(c[0]), "+f"(c[1]), "+f"(c[2]), "+f"(c[3])
        : "r"(a[0]), "r"(a[1]), "r"(a[2]), "r"(a[3]), "r"(b[0]), "r"(b[1]));
}
__device__ __forceinline__ uint32_t smem_u32(const void* p) {
    uint32_t a;
    asm("{ .reg .u64 t; cvta.to.shared.u64 t, %1; cvt.u32.u64 %0, t; }"
        : "=r"(a) : "l"(p));
    return a;
}
__device__ __forceinline__ void cp16(uint32_t dst, const void* src) {
    asm volatile("cp.async.cg.shared.global [%0], [%1], 16;"
                 :: "r"(dst), "l"(src) : "memory");
}
__device__ __forceinline__ void cp_commit() {
    asm volatile("cp.async.commit_group;" ::: "memory");
}
__device__ __forceinline__ void cp_wait0() {
    asm volatile("cp.async.wait_group 0;" ::: "memory");
}
__device__ __forceinline__ void cp_wait1() {
    asm volatile("cp.async.wait_group 1;" ::: "memory");
}

// ---------------------------------------------------------------------------
// prep: pack fp32 -> bf16 hi/lo words. which 0..2 = q/k/v input, 3..6 = W.
// ---------------------------------------------------------------------------
__global__ __launch_bounds__(256) void pack_kernel(const float4* __restrict__ src,
                                                   int which)
{
    uint4* dh; uint4* dl; int n8;
    if (which < 3) {
        dh = (uint4*)g_inh + (size_t)which * (NTOK * E_ / 8);
        dl = (uint4*)g_inl + (size_t)which * (NTOK * E_ / 8);
        n8 = NTOK * E_ / 8;
    } else {
        dh = (uint4*)g_Wh + (size_t)(which - 3) * (E_ * E_ / 8);
        dl = (uint4*)g_Wl + (size_t)(which - 3) * (E_ * E_ / 8);
        n8 = E_ * E_ / 8;
    }
    int g = blockIdx.x * 256 + threadIdx.x;
    if (g >= n8) return;
    float4 a = src[2 * g], b = src[2 * g + 1];
    uint4 h, l;
    split_pack(a.x, a.y, h.x, l.x);
    split_pack(a.z, a.w, h.y, l.y);
    split_pack(b.x, b.y, h.z, l.z);
    split_pack(b.z, b.w, h.w, l.w);
    dh[g] = h; dl[g] = l;
}

// ---------------------------------------------------------------------------
// prep2: transpose-pack V: g_V fp32 [bh][L][D] -> g_Vp [bh][D][L/2] words,
// word(d, rp) = pack(V[2rp][d], V[2rp+1][d]). One block per (jt, bh).
// ---------------------------------------------------------------------------
__global__ __launch_bounds__(256) void vpack_kernel()
{
    __shared__ float t[64][65];
    const int jt = blockIdx.x, bh = blockIdx.y, tid = threadIdx.x;
    const float* Vp = g_V + ((size_t)bh * L_ + jt * 64) * D_;
#pragma unroll
    for (int c = 0; c < 4; c++) {
        int id = c * 256 + tid;
        int r = id >> 4, d4 = (id & 15) << 2;
        float4 v = *(const float4*)&Vp[(size_t)r * D_ + d4];
        t[r][d4] = v.x; t[r][d4 + 1] = v.y; t[r][d4 + 2] = v.z; t[r][d4 + 3] = v.w;
    }
    __syncthreads();
    const int rp = tid & 31;
#pragma unroll
    for (int i = 0; i < 8; i++) {
        int d = (tid >> 5) + 8 * i;
        uint32_t h, l;
        split_pack(t[2 * rp][d], t[2 * rp + 1][d], h, l);
        size_t idx = ((size_t)bh * 64 + d) * (L_ / 2) + jt * 32 + rp;
        g_Vph[idx] = h;
        g_Vpl[idx] = l;
    }
}

// ---------------------------------------------------------------------------
// 3xBF16 GEMM body (CTA 128x128, k16 chunks, 8 warps of 64x32).
// Packed smem [row][PSTR] stride 12 (8 data words + 4 pad): conflict-free.
// ---------------------------------------------------------------------------
constexpr int BK = 16;
constexpr int NKC = E_ / BK;      // 64
constexpr int PSTR = 12;

struct GemmSmem {
    uint32_t Ah[128][PSTR];
    uint32_t Al[128][PSTR];
    uint32_t Bh[128][PSTR];
    uint32_t Bl[128][PSTR];
};
constexpr int STAGE_B = (int)sizeof(GemmSmem);     // 24576
constexpr int GEMM_SMEM = 3 * STAGE_B;             // 73728

__device__ __forceinline__ void mma_chunk(const GemmSmem& s, int wm, int wn,
                                          int gr, int tig, float acc[4][4][4]) {
    uint32_t ah[4][4], al[4][4];
#pragma unroll
    for (int i = 0; i < 4; i++) {
        const int r = wm + 16 * i + gr;
        ah[i][0] = s.Ah[r][tig];     ah[i][1] = s.Ah[r + 8][tig];
        ah[i][2] = s.Ah[r][tig + 4]; ah[i][3] = s.Ah[r + 8][tig + 4];
        al[i][0] = s.Al[r][tig];     al[i][1] = s.Al[r + 8][tig];
        al[i][2] = s.Al[r][tig + 4]; al[i][3] = s.Al[r + 8][tig + 4];
    }
#pragma unroll
    for (int j = 0; j < 4; j++) {
        const int cn = wn + 8 * j + gr;
        uint32_t bh[2] = {s.Bh[cn][tig], s.Bh[cn][tig + 4]};
        uint32_t bl[2] = {s.Bl[cn][tig], s.Bl[cn][tig + 4]};
#pragma unroll
        for (int i = 0; i < 4; i++) {
            mma_bf16(acc[i][j], ah[i], bh);
            mma_bf16(acc[i][j], ah[i], bl);
            mma_bf16(acc[i][j], al[i], bh);
        }
    }
}

// ---------------------------------------------------------------------------
// Projection GEMM (cp.async 3-stage). z: 0=Q (fp32 out), 1=K (packed out),
// 2=V (fp32 out, transposed-packed later by vpack_kernel).
// ---------------------------------------------------------------------------
__global__ __launch_bounds__(256, 2) void proj_tc()
{
    extern __shared__ uint8_t gsm_raw[];
    const uint32_t sb = smem_u32(gsm_raw);
    const int z = blockIdx.z;
    const uint32_t* Xh = g_inh + (size_t)z * (NTOK * E_ / 2);
    const uint32_t* Xl = g_inl + (size_t)z * (NTOK * E_ / 2);
    const uint32_t* WhP = g_Wh + (size_t)z * (E_ * E_ / 2);
    const uint32_t* WlP = g_Wl + (size_t)z * (E_ * E_ / 2);

    const int tid = threadIdx.x, wid = tid >> 5, lane = tid & 31;
    const int gr = lane >> 2, tig = lane & 3;
    const int wm = (wid & 1) * 64, wn = (wid >> 1) * 32;
    const int m0 = blockIdx.y * 128, n0 = blockIdx.x * 128;

    const int row = tid >> 1, half = tid & 1;
    const size_t srcA = (size_t)(m0 + row) * (E_ / 2) + half * 4;
    const size_t srcB = (size_t)(n0 + row) * (E_ / 2) + half * 4;
    const uint32_t dOff = (uint32_t)(row * PSTR + half * 4) * 4;

    auto issue = [&](int kc) {
        const uint32_t base = sb + (kc % 3) * STAGE_B;
        const size_t o = (size_t)kc * 8;
        cp16(base + dOff,          Xh + srcA + o);
        cp16(base + 6144 + dOff,   Xl + srcA + o);
        cp16(base + 12288 + dOff,  WhP + srcB + o);
        cp16(base + 18432 + dOff,  WlP + srcB + o);
        cp_commit();
    };
    issue(0); issue(1);

    float acc[4][4][4] = {};
    for (int kc = 0; kc < NKC; kc++) {
        if (kc == NKC - 1) cp_wait0(); else cp_wait1();
        __syncthreads();
        if (kc + 2 < NKC) issue(kc + 2);
        mma_chunk(*(const GemmSmem*)(gsm_raw + (kc % 3) * STAGE_B),
                  wm, wn, gr, tig, acc);
    }

#pragma unroll
    for (int i = 0; i < 4; i++) {
        const int m_a = m0 + wm + 16 * i + gr;
        const int m_b = m_a + 8;
        const int ba = m_a >> 11, la = m_a & (L_ - 1);
        const int bb = m_b >> 11, lb = m_b & (L_ - 1);
#pragma unroll
        for (int j = 0; j < 4; j++) {
            const int col = n0 + wn + 8 * j + 2 * tig;
            const int hg = col >> 6, d = col & 63;
            if (z == 1) {   // K: write packed
                uint32_t ph, pl;
                size_t ia = ((size_t)(ba * H_ + hg) * L_ + la) * 32 + (d >> 1);
                split_pack(acc[i][j][0], acc[i][j][1], ph, pl);
                g_Khg[ia] = ph; g_Klg[ia] = pl;
                size_t ib = ((size_t)(bb * H_ + hg) * L_ + lb) * 32 + (d >> 1);
                split_pack(acc[i][j][2], acc[i][j][3], ph, pl);
                g_Khg[ib] = ph; g_Klg[ib] = pl;
            } else {        // Q or V: fp32
                float* Out = (z == 0) ? g_Q : g_V;
                *(float2*)&Out[((size_t)(ba * H_ + hg) * L_ + la) * D_ + d] =
                    make_float2(acc[i][j][0], acc[i][j][1]);
                *(float2*)&Out[((size_t)(bb * H_ + hg) * L_ + lb) * D_ + d] =
                    make_float2(acc[i][j][2], acc[i][j][3]);
            }
        }
    }
}

// ---------------------------------------------------------------------------
// Output projection: A = packed Oh (from attn), B = packed Wo. cp.async.
// ---------------------------------------------------------------------------
__global__ __launch_bounds__(256, 2) void outproj_tc(float* __restrict__ out)
{
    extern __shared__ uint8_t gsm_raw[];
    const uint32_t sb = smem_u32(gsm_raw);
    const uint32_t* WhP = g_Wh + (size_t)3 * (E_ * E_ / 2);
    const uint32_t* WlP = g_Wl + (size_t)3 * (E_ * E_ / 2);

    const int tid = threadIdx.x, wid = tid >> 5, lane = tid & 31;
    const int gr = lane >> 2, tig = lane & 3;
    const int wm = (wid & 1) * 64, wn = (wid >> 1) * 32;
    const int m0 = blockIdx.y * 128, n0 = blockIdx.x * 128;

    const int row = tid >> 1, half = tid & 1;
    const int m = m0 + row, bb_ = m >> 11, ll = m & (L_ - 1);
    const size_t srcB = (size_t)(n0 + row) * (E_ / 2) + half * 4;
    const uint32_t dOff = (uint32_t)(row * PSTR + half * 4) * 4;

    auto issue = [&](int kc) {
        const uint32_t base = sb + (kc % 3) * STAGE_B;
        const int hg = kc >> 2;                    // head = kc*16/64
        const int w0 = (kc & 3) * 8 + half * 4;    // word within head row
        const size_t sa = ((size_t)(bb_ * H_ + hg) * L_ + ll) * 32 + w0;
        const size_t ob = (size_t)kc * 8;
        cp16(base + dOff,          g_Ohh + sa);
        cp16(base + 6144 + dOff,   g_Ohl + sa);
        cp16(base + 12288 + dOff,  WhP + srcB + ob);
        cp16(base + 18432 + dOff,  WlP + srcB + ob);
        cp_commit();
    };
    issue(0); issue(1);

    float acc[4][4][4] = {};
    for (int kc = 0; kc < NKC; kc++) {
        if (kc == NKC - 1) cp_wait0(); else cp_wait1();
        __syncthreads();
        if (kc + 2 < NKC) issue(kc + 2);
        mma_chunk(*(const GemmSmem*)(gsm_raw + (kc % 3) * STAGE_B),
                  wm, wn, gr, tig, acc);
    }

#pragma unroll
    for (int i = 0; i < 4; i++) {
        const int m_a = m0 + wm + 16 * i + gr;
#pragma unroll
        for (int j = 0; j < 4; j++) {
            const int col = n0 + wn + 8 * j + 2 * tig;
            *(float2*)&out[(size_t)m_a * E_ + col] =
                make_float2(acc[i][j][0], acc[i][j][1]);
            *(float2*)&out[(size_t)(m_a + 8) * E_ + col] =
                make_float2(acc[i][j][2], acc[i][j][3]);
        }
    }
}

// ---------------------------------------------------------------------------
// Tensor-core fused causal attention, cp.async double-buffered K/V tiles.
// CTA = 128 Q-rows; 8 warps (m16 x n64); jt-steps of 64 K-columns.
// smem words: K/V tiles 2 bufs x (Kh,Kl,Vh,Vl)[64][36]; P2h/P2l [128][36]; sl.
// One __syncthreads per jt; cp.async for jt+1 overlaps full compute of jt.
// ---------------------------------------------------------------------------
__global__ __launch_bounds__(256, 2) void attn_tc(float* __restrict__ attn_base)
{
    extern __shared__ uint32_t usm[];
    const uint32_t sb = smem_u32(usm);
    uint32_t* P2h = usm + 18432;
    uint32_t* P2l = usm + 23040;
    float*    sl  = (float*)(usm + 27648);

    const int bh = blockIdx.y;
    const int it = (int)gridDim.x - 1 - (int)blockIdx.x;   // heavy tiles first
    const int q0 = it * 128;
    const int tid = threadIdx.x, wid = tid >> 5, lane = tid & 31;
    const int gr = lane >> 2, tig = lane & 3;
    const int wm = wid * 16;

    const float* Qp = g_Q + (size_t)bh * L_ * D_;
    float* attn = attn_base + (size_t)bh * L_ * L_;

    // Q A-fragments, pre-split packed bf16x2 (4 k16-chunks over D=64)
    uint32_t qh[4][4], ql[4][4];
    const int grow0 = q0 + wm + gr, grow1 = grow0 + 8;
#pragma unroll
    for (int kc = 0; kc < 4; kc++) {
        float2 q00 = *(const float2*)&Qp[(size_t)grow0 * D_ + kc * 16 + 2 * tig];
        float2 q10 = *(const float2*)&Qp[(size_t)grow1 * D_ + kc * 16 + 2 * tig];
        float2 q01 = *(const float2*)&Qp[(size_t)grow0 * D_ + kc * 16 + 2 * tig + 8];
        float2 q11 = *(const float2*)&Qp[(size_t)grow1 * D_ + kc * 16 + 2 * tig + 8];
        split_pack(q00.x, q00.y, qh[kc][0], ql[kc][0]);
        split_pack(q10.x, q10.y, qh[kc][1], ql[kc][1]);
        split_pack(q01.x, q01.y, qh[kc][2], ql[kc][2]);
        split_pack(q11.x, q11.y, qh[kc][3], ql[kc][3]);
    }

    const int ntiles = 2 * it + 2;
    const float scale = 0.125f;

    // cp.async issue of one K/V tile (hi+lo) into buffer jt&1.
    auto issue = [&](int jt) {
        const uint32_t kbase = sb + (jt & 1) * 36864;
#pragma unroll
        for (int c = 0; c < 2; c++) {
            int s = c * 256 + tid;            // 0..511
            int r = s >> 3, seg = (s & 7) * 4;
            uint32_t doff = (uint32_t)(r * 36 + seg) * 4;
            size_t ksrc = ((size_t)bh * L_ + jt * 64 + r) * 32 + seg;
            size_t vsrc = ((size_t)bh * 64 + r) * (L_ / 2) + jt * 32 + seg;
            cp16(kbase + doff,         g_Khg + ksrc);
            cp16(kbase + 9216 + doff,  g_Klg + ksrc);
            cp16(kbase + 18432 + doff, g_Vph + vsrc);
            cp16(kbase + 27648 + doff, g_Vpl + vsrc);
        }
        cp_commit();
    };
    issue(0);

    float l0 = 0.f, l1 = 0.f;
    float oa[8][4] = {};

    for (int jt = 0; jt < ntiles; jt++) {
        cp_wait0();
        __syncthreads();   // tile jt landed; all warps done with buf (jt+1)&1
        if (jt + 1 < ntiles) issue(jt + 1);

        const uint32_t* Kh = usm + (jt & 1) * 9216;
        const uint32_t* Kl = Kh + 2304;
        const uint32_t* Vh = Kh + 4608;
        const uint32_t* Vl = Kh + 6912;

        // QK + exp fused, nt-pairs
#pragma unroll
        for (int np = 0; np < 4; np++) {
            float sc[2][4] = {};
#pragma unroll
            for (int kc = 0; kc < 4; kc++) {
#pragma unroll
                for (int u = 0; u < 2; u++) {
                    const int nt = 2 * np + u;
                    const int rb = (nt * 8 + gr) * 36 + kc * 8 + tig;
                    uint32_t bhv[2] = {Kh[rb], Kh[rb + 4]};
                    uint32_t blv[2] = {Kl[rb], Kl[rb + 4]};
                    mma_bf16(sc[u], qh[kc], bhv);
                    mma_bf16(sc[u], qh[kc], blv);
                    mma_bf16(sc[u], ql[kc], bhv);
                }
            }
#pragma unroll
            for (int u = 0; u < 2; u++) {
                const int nt = 2 * np + u;
                int jc = jt * 64 + nt * 8 + 2 * tig;
                float p0 = __expf(sc[u][0] * scale); if (jc     > grow0) p0 = 0.f;
                float p1 = __expf(sc[u][1] * scale); if (jc + 1 > grow0) p1 = 0.f;
                float p2 = __expf(sc[u][2] * scale); if (jc     > grow1) p2 = 0.f;
                float p3 = __expf(sc[u][3] * scale); if (jc + 1 > grow1) p3 = 0.f;
                l0 += p0 + p1;
                l1 += p2 + p3;
                uint32_t h, l;
                split_pack(p0, p1, h, l);
                P2h[(wm + gr) * 36 + nt * 4 + tig] = h;
                P2l[(wm + gr) * 36 + nt * 4 + tig] = l;
                split_pack(p2, p3, h, l);
                P2h[(wm + gr + 8) * 36 + nt * 4 + tig] = h;
                P2l[(wm + gr + 8) * 36 + nt * 4 + tig] = l;
                *(float2*)&attn[(size_t)grow0 * L_ + jc] = make_float2(p0, p1);
                *(float2*)&attn[(size_t)grow1 * L_ + jc] = make_float2(p2, p3);
            }
        }
        __syncwarp();   // P2 rows are warp-private

        // O += P V
#pragma unroll
        for (int kc = 0; kc < 4; kc++) {
            const int a0 = (wm + gr) * 36 + kc * 8 + tig;
            const int a1 = (wm + gr + 8) * 36 + kc * 8 + tig;
            uint32_t ph[4]  = {P2h[a0], P2h[a1], P2h[a0 + 4], P2h[a1 + 4]};
            uint32_t plo[4] = {P2l[a0], P2l[a1], P2l[a0 + 4], P2l[a1 + 4]};
#pragma unroll
            for (int nt = 0; nt < 8; nt++) {
                const int vb = (nt * 8 + gr) * 36 + kc * 8 + tig;
                uint32_t bhv[2] = {Vh[vb], Vh[vb + 4]};
                uint32_t blv[2] = {Vl[vb], Vl[vb + 4]};
                mma_bf16(oa[nt], ph, bhv);
                mma_bf16(oa[nt], ph, blv);
                mma_bf16(oa[nt], plo, bhv);
            }
        }
    }

    // row sums: reduce lane partials over the quad
    l0 += __shfl_xor_sync(0xffffffffu, l0, 1);
    l0 += __shfl_xor_sync(0xffffffffu, l0, 2);
    l1 += __shfl_xor_sync(0xffffffffu, l1, 1);
    l1 += __shfl_xor_sync(0xffffffffu, l1, 2);
    const float inv0 = 1.f / l0, inv1 = 1.f / l1;
    if (tig == 0) {
        sl[wm + gr] = inv0;
        sl[wm + gr + 8] = inv1;
    }
    // normalized O -> packed global (feeds outproj cp.async)
#pragma unroll
    for (int nt = 0; nt < 8; nt++) {
        uint32_t h, l;
        split_pack(oa[nt][0] * inv0, oa[nt][1] * inv0, h, l);
        size_t ia = ((size_t)bh * L_ + grow0) * 32 + nt * 4 + tig;
        g_Ohh[ia] = h; g_Ohl[ia] = l;
        split_pack(oa[nt][2] * inv1, oa[nt][3] * inv1, h, l);
        size_t ib = ((size_t)bh * L_ + grow1) * 32 + nt * 4 + tig;
        g_Ohh[ib] = h; g_Ohl[ib] = l;
    }
    __syncthreads();   // sl visible; all P gmem writes done CTA-wide

    // normalize lower tiles in place; zero-fill upper triangle
    for (int j2 = 0; j2 < ntiles; j2++) {
#pragma unroll
        for (int c = 0; c < 8; c++) {
            int id = c * 256 + tid;
            int r = id >> 4, c4 = (id & 15) << 2;
            float inv = sl[r];
            float* p = &attn[(size_t)(q0 + r) * L_ + j2 * 64 + c4];
            float4 v = *(float4*)p;
            v.x *= inv; v.y *= inv; v.z *= inv; v.w *= inv;
            *(float4*)p = v;
        }
    }
    const float4 z4 = make_float4(0.f, 0.f, 0.f, 0.f);
    for (int j2 = ntiles; j2 < L_ / 64; j2++) {
#pragma unroll
        for (int c = 0; c < 8; c++) {
            int id = c * 256 + tid;
            int r = id >> 4, c4 = (id & 15) << 2;
            *(float4*)&attn[(size_t)(q0 + r) * L_ + j2 * 64 + c4] = z4;
        }
    }
}

constexpr int ATTN_SMEM = (27648 + 128) * 4;   // 111104 B

// ---------------------------------------------------------------------------
extern "C" void kernel_launch(void* const* d_in, const int* in_sizes, int n_in,
                              void* d_out, int out_size)
{
    const float* qkv[3] = {nullptr, nullptr, nullptr};
    const float* Ws[4]  = {nullptr, nullptr, nullptr, nullptr};
    int nqkv = 0, nw = 0;
    for (int i = 0; i < n_in; i++) {
        if (in_sizes[i] == NTOK * E_) { if (nqkv < 3) qkv[nqkv++] = (const float*)d_in[i]; }
        else if (in_sizes[i] == E_ * E_) { if (nw < 4) Ws[nw++] = (const float*)d_in[i]; }
    }
    float* out  = (float*)d_out;
    float* attn = out + (size_t)B_ * L_ * E_;

    cudaFuncSetAttribute(proj_tc, cudaFuncAttributeMaxDynamicSharedMemorySize, GEMM_SMEM);
    cudaFuncSetAttribute(outproj_tc, cudaFuncAttributeMaxDynamicSharedMemorySize, GEMM_SMEM);
    cudaFuncSetAttribute(attn_tc, cudaFuncAttributeMaxDynamicSharedMemorySize, ATTN_SMEM);

    for (int i = 0; i < 3; i++)
        pack_kernel<<<NTOK * E_ / 8 / 256, 256>>>((const float4*)qkv[i], i);
    for (int i = 0; i < 4; i++)
        pack_kernel<<<E_ * E_ / 8 / 256, 256>>>((const float4*)Ws[i], 3 + i);

    proj_tc<<<dim3(E_ / 128, NTOK / 128, 3), 256, GEMM_SMEM>>>();
    vpack_kernel<<<dim3(L_ / 64, BH), 256>>>();
    attn_tc<<<dim3(L_ / 128, BH), 256, ATTN_SMEM>>>(attn);
    outproj_tc<<<dim3(E_ / 128, NTOK / 128), 256, GEMM_SMEM>>>(out);
}

// round 12
// speedup vs baseline: 2.0268x; 1.0644x over previous
#include <cuda_runtime.h>
#include <cstdint>

// ---------------------------------------------------------------------------
// MHA forward: out = (softmax_causal(QK^T/sqrt(D)) V) Wo^T,  also emit attn.
// B=4, L=2048, E=1024, H=16, D=64.
// d_out layout: [out: B*L*E floats][attn: B*H*L*L floats]
// 3xBF16 m16n8k16 everywhere; operands pre-packed bf16 hi/lo in gmem;
// GEMMs cp.async 3-stage; attention cp.async double-buffered.
// R12: ALL fragment loads via ldmatrix.m8n8.x4 (R11 was frag-LDS issue-bound:
// 256 LDS vs 192 mma per attention jt, 48 LDS vs 48 mma per GEMM chunk).
// ---------------------------------------------------------------------------

constexpr int B_ = 4, L_ = 2048, E_ = 1024, H_ = 16, D_ = 64;
constexpr int BH   = B_ * H_;     // 64
constexpr int NTOK = B_ * L_;     // 8192

// fp32 scratch
__device__ float g_Q[BH * L_ * D_];
__device__ float g_V[BH * L_ * D_];
// packed bf16 hi/lo operands
__device__ uint32_t g_inh[3 * NTOK * E_ / 2], g_inl[3 * NTOK * E_ / 2];
__device__ uint32_t g_Wh[4 * E_ * E_ / 2],   g_Wl[4 * E_ * E_ / 2];
__device__ uint32_t g_Khg[BH * L_ * D_ / 2], g_Klg[BH * L_ * D_ / 2];
__device__ uint32_t g_Vph[BH * D_ * L_ / 2], g_Vpl[BH * D_ * L_ / 2];
__device__ uint32_t g_Ohh[BH * L_ * D_ / 2], g_Ohl[BH * L_ * D_ / 2];

// ---------------------------------------------------------------------------
__device__ __forceinline__ uint32_t pack2(float x0, float x1) {
    uint32_t r;
    asm("cvt.rn.bf16x2.f32 %0, %1, %2;" : "=r"(r) : "f"(x1), "f"(x0));
    return r;
}
__device__ __forceinline__ void split_pack(float x0, float x1,
                                           uint32_t& h, uint32_t& l) {
    h = pack2(x0, x1);
    float h0 = __uint_as_float(h << 16);
    float h1 = __uint_as_float(h & 0xffff0000u);
    l = pack2(x0 - h0, x1 - h1);
}
__device__ __forceinline__ void mma_bf16(float* c, const uint32_t* a,
                                         const uint32_t* b) {
    asm volatile(
        "mma.sync.aligned.m16n8k16.row.col.f32.bf16.bf16.f32 "
        "{%0,%1,%2,%3}, {%4,%5,%6,%7}, {%8,%9}, {%0,%1,%2,%3};"
        : "+f"(c[0]), "+f"(c[1]), "+f"(c[2]), "+f"(c[3])
        : "r"(a[0]), "r"(a[1]), "r"(a[2]), "r"(a[3]), "r"(b[0]), "r"(b[1]));
}
__device__ __forceinline__ void ldm4(uint32_t* r, uint32_t a) {
    asm volatile("ldmatrix.sync.aligned.m8n8.x4.shared.b16 {%0,%1,%2,%3}, [%4];"
        : "=r"(r[0]), "=r"(r[1]), "=r"(r[2]), "=r"(r[3]) : "r"(a));
}
__device__ __forceinline__ uint32_t smem_u32(const void* p) {
    uint32_t a;
    asm("{ .reg .u64 t; cvta.to.shared.u64 t, %1; cvt.u32.u64 %0, t; }"
        : "=r"(a) : "l"(p));
    return a;
}
__device__ __forceinline__ void cp16(uint32_t dst, const void* src) {
    asm volatile("cp.async.cg.shared.global [%0], [%1], 16;"
                 :: "r"(dst), "l"(src) : "memory");
}
__device__ __forceinline__ void cp_commit() {
    asm volatile("cp.async.commit_group;" ::: "memory");
}
__device__ __forceinline__ void cp_wait0() {
    asm volatile("cp.async.wait_group 0;" ::: "memory");
}
__device__ __forceinline__ void cp_wait1() {
    asm volatile("cp.async.wait_group 1;" ::: "memory");
}

// ---------------------------------------------------------------------------
// prep: pack fp32 -> bf16 hi/lo words. which 0..2 = q/k/v input, 3..6 = W.
// ---------------------------------------------------------------------------
__global__ __launch_bounds__(256) void pack_kernel(const float4* __restrict__ src,
                                                   int which)
{
    uint4* dh; uint4* dl; int n8;
    if (which < 3) {
        dh = (uint4*)g_inh + (size_t)which * (NTOK * E_ / 8);
        dl = (uint4*)g_inl + (size_t)which * (NTOK * E_ / 8);
        n8 = NTOK * E_ / 8;
    } else {
        dh = (uint4*)g_Wh + (size_t)(which - 3) * (E_ * E_ / 8);
        dl = (uint4*)g_Wl + (size_t)(which - 3) * (E_ * E_ / 8);
        n8 = E_ * E_ / 8;
    }
    int g = blockIdx.x * 256 + threadIdx.x;
    if (g >= n8) return;
    float4 a = src[2 * g], b = src[2 * g + 1];
    uint4 h, l;
    split_pack(a.x, a.y, h.x, l.x);
    split_pack(a.z, a.w, h.y, l.y);
    split_pack(b.x, b.y, h.z, l.z);
    split_pack(b.z, b.w, h.w, l.w);
    dh[g] = h; dl[g] = l;
}

// ---------------------------------------------------------------------------
// prep2: transpose-pack V: g_V fp32 [bh][L][D] -> g_Vp [bh][D][L/2] words,
// word(d, rp) = pack(V[2rp][d], V[2rp+1][d]). One block per (jt, bh).
// ---------------------------------------------------------------------------
__global__ __launch_bounds__(256) void vpack_kernel()
{
    __shared__ float t[64][65];
    const int jt = blockIdx.x, bh = blockIdx.y, tid = threadIdx.x;
    const float* Vp = g_V + ((size_t)bh * L_ + jt * 64) * D_;
#pragma unroll
    for (int c = 0; c < 4; c++) {
        int id = c * 256 + tid;
        int r = id >> 4, d4 = (id & 15) << 2;
        float4 v = *(const float4*)&Vp[(size_t)r * D_ + d4];
        t[r][d4] = v.x; t[r][d4 + 1] = v.y; t[r][d4 + 2] = v.z; t[r][d4 + 3] = v.w;
    }
    __syncthreads();
    const int rp = tid & 31;
#pragma unroll
    for (int i = 0; i < 8; i++) {
        int d = (tid >> 5) + 8 * i;
        uint32_t h, l;
        split_pack(t[2 * rp][d], t[2 * rp + 1][d], h, l);
        size_t idx = ((size_t)bh * 64 + d) * (L_ / 2) + jt * 32 + rp;
        g_Vph[idx] = h;
        g_Vpl[idx] = l;
    }
}

// ---------------------------------------------------------------------------
// 3xBF16 GEMM body (CTA 128x128, k16 chunks, 8 warps of 64x32).
// Packed smem [row][PSTR] stride 12 words (48B): ldmatrix 8-row phases hit
// banks 12r mod 32 = {0,12,24,4,16,28,8,20} x4-wide -> all 32, conflict-free.
// ---------------------------------------------------------------------------
constexpr int BK = 16;
constexpr int NKC = E_ / BK;      // 64
constexpr int PSTR = 12;

constexpr int STAGE_B = 4 * 128 * PSTR * 4;        // 24576 (Ah,Al,Bh,Bl)
constexpr int GEMM_SMEM = 3 * STAGE_B;             // 73728

// ldmatrix-based chunk: 12 LDSM.x4 + 48 mma.
__device__ __forceinline__ void mma_chunk_ldm(uint32_t stage, int wm, int wn,
                                              uint32_t aoff, uint32_t boff,
                                              float acc[4][4][4]) {
    uint32_t ah[4][4], al[4][4], bh[4][2], bl[4][2];
#pragma unroll
    for (int i = 0; i < 4; i++) {
        uint32_t addr = stage + (uint32_t)((wm + 16 * i) * PSTR * 4) + aoff;
        ldm4(ah[i], addr);
        ldm4(al[i], addr + 6144);
    }
#pragma unroll
    for (int jp = 0; jp < 2; jp++) {
        uint32_t addr = stage + 12288 + (uint32_t)((wn + 16 * jp) * PSTR * 4) + boff;
        uint32_t th[4], tl[4];
        ldm4(th, addr);
        ldm4(tl, addr + 6144);
        bh[2 * jp][0] = th[0]; bh[2 * jp][1] = th[1];
        bh[2 * jp + 1][0] = th[2]; bh[2 * jp + 1][1] = th[3];
        bl[2 * jp][0] = tl[0]; bl[2 * jp][1] = tl[1];
        bl[2 * jp + 1][0] = tl[2]; bl[2 * jp + 1][1] = tl[3];
    }
#pragma unroll
    for (int j = 0; j < 4; j++)
#pragma unroll
        for (int i = 0; i < 4; i++) {
            mma_bf16(acc[i][j], ah[i], bh[j]);
            mma_bf16(acc[i][j], ah[i], bl[j]);
            mma_bf16(acc[i][j], al[i], bh[j]);
        }
}

// lane offsets (bytes) for ldmatrix addressing
__device__ __forceinline__ uint32_t a_lane_off(int lane) {
    int row = (lane & 7) + ((lane >> 3) & 1) * 8;
    int cw  = (lane >> 4) * 4;
    return (uint32_t)((row * PSTR + cw) * 4);
}
__device__ __forceinline__ uint32_t b_lane_off(int lane) {
    int row = (lane & 7) + (lane >> 4) * 8;
    int cw  = ((lane >> 3) & 1) * 4;
    return (uint32_t)((row * PSTR + cw) * 4);
}

// ---------------------------------------------------------------------------
// Projection GEMM (cp.async 3-stage). z: 0=Q (fp32), 1=K (packed), 2=V (fp32).
// ---------------------------------------------------------------------------
__global__ __launch_bounds__(256, 2) void proj_tc()
{
    extern __shared__ uint8_t gsm_raw[];
    const uint32_t sb = smem_u32(gsm_raw);
    const int z = blockIdx.z;
    const uint32_t* Xh = g_inh + (size_t)z * (NTOK * E_ / 2);
    const uint32_t* Xl = g_inl + (size_t)z * (NTOK * E_ / 2);
    const uint32_t* WhP = g_Wh + (size_t)z * (E_ * E_ / 2);
    const uint32_t* WlP = g_Wl + (size_t)z * (E_ * E_ / 2);

    const int tid = threadIdx.x, wid = tid >> 5, lane = tid & 31;
    const int gr = lane >> 2, tig = lane & 3;
    const int wm = (wid & 1) * 64, wn = (wid >> 1) * 32;
    const int m0 = blockIdx.y * 128, n0 = blockIdx.x * 128;
    const uint32_t aoff = a_lane_off(lane), boff = b_lane_off(lane);

    const int row = tid >> 1, half = tid & 1;
    const size_t srcA = (size_t)(m0 + row) * (E_ / 2) + half * 4;
    const size_t srcB = (size_t)(n0 + row) * (E_ / 2) + half * 4;
    const uint32_t dOff = (uint32_t)(row * PSTR + half * 4) * 4;

    auto issue = [&](int kc) {
        const uint32_t base = sb + (kc % 3) * STAGE_B;
        const size_t o = (size_t)kc * 8;
        cp16(base + dOff,          Xh + srcA + o);
        cp16(base + 6144 + dOff,   Xl + srcA + o);
        cp16(base + 12288 + dOff,  WhP + srcB + o);
        cp16(base + 18432 + dOff,  WlP + srcB + o);
        cp_commit();
    };
    issue(0); issue(1);

    float acc[4][4][4] = {};
    for (int kc = 0; kc < NKC; kc++) {
        if (kc == NKC - 1) cp_wait0(); else cp_wait1();
        __syncthreads();
        if (kc + 2 < NKC) issue(kc + 2);
        mma_chunk_ldm(sb + (kc % 3) * STAGE_B, wm, wn, aoff, boff, acc);
    }

#pragma unroll
    for (int i = 0; i < 4; i++) {
        const int m_a = m0 + wm + 16 * i + gr;
        const int m_b = m_a + 8;
        const int ba = m_a >> 11, la = m_a & (L_ - 1);
        const int bb = m_b >> 11, lb = m_b & (L_ - 1);
#pragma unroll
        for (int j = 0; j < 4; j++) {
            const int col = n0 + wn + 8 * j + 2 * tig;
            const int hg = col >> 6, d = col & 63;
            if (z == 1) {   // K: write packed
                uint32_t ph, pl;
                size_t ia = ((size_t)(ba * H_ + hg) * L_ + la) * 32 + (d >> 1);
                split_pack(acc[i][j][0], acc[i][j][1], ph, pl);
                g_Khg[ia] = ph; g_Klg[ia] = pl;
                size_t ib = ((size_t)(bb * H_ + hg) * L_ + lb) * 32 + (d >> 1);
                split_pack(acc[i][j][2], acc[i][j][3], ph, pl);
                g_Khg[ib] = ph; g_Klg[ib] = pl;
            } else {        // Q or V: fp32
                float* Out = (z == 0) ? g_Q : g_V;
                *(float2*)&Out[((size_t)(ba * H_ + hg) * L_ + la) * D_ + d] =
                    make_float2(acc[i][j][0], acc[i][j][1]);
                *(float2*)&Out[((size_t)(bb * H_ + hg) * L_ + lb) * D_ + d] =
                    make_float2(acc[i][j][2], acc[i][j][3]);
            }
        }
    }
}

// ---------------------------------------------------------------------------
// Output projection: A = packed Oh (from attn), B = packed Wo. cp.async.
// ---------------------------------------------------------------------------
__global__ __launch_bounds__(256, 2) void outproj_tc(float* __restrict__ out)
{
    extern __shared__ uint8_t gsm_raw[];
    const uint32_t sb = smem_u32(gsm_raw);
    const uint32_t* WhP = g_Wh + (size_t)3 * (E_ * E_ / 2);
    const uint32_t* WlP = g_Wl + (size_t)3 * (E_ * E_ / 2);

    const int tid = threadIdx.x, wid = tid >> 5, lane = tid & 31;
    const int gr = lane >> 2, tig = lane & 3;
    const int wm = (wid & 1) * 64, wn = (wid >> 1) * 32;
    const int m0 = blockIdx.y * 128, n0 = blockIdx.x * 128;
    const uint32_t aoff = a_lane_off(lane), boff = b_lane_off(lane);

    const int row = tid >> 1, half = tid & 1;
    const int m = m0 + row, bb_ = m >> 11, ll = m & (L_ - 1);
    const size_t srcB = (size_t)(n0 + row) * (E_ / 2) + half * 4;
    const uint32_t dOff = (uint32_t)(row * PSTR + half * 4) * 4;

    auto issue = [&](int kc) {
        const uint32_t base = sb + (kc % 3) * STAGE_B;
        const int hg = kc >> 2;
        const int w0 = (kc & 3) * 8 + half * 4;
        const size_t sa = ((size_t)(bb_ * H_ + hg) * L_ + ll) * 32 + w0;
        const size_t ob = (size_t)kc * 8;
        cp16(base + dOff,          g_Ohh + sa);
        cp16(base + 6144 + dOff,   g_Ohl + sa);
        cp16(base + 12288 + dOff,  WhP + srcB + ob);
        cp16(base + 18432 + dOff,  WlP + srcB + ob);
        cp_commit();
    };
    issue(0); issue(1);

    float acc[4][4][4] = {};
    for (int kc = 0; kc < NKC; kc++) {
        if (kc == NKC - 1) cp_wait0(); else cp_wait1();
        __syncthreads();
        if (kc + 2 < NKC) issue(kc + 2);
        mma_chunk_ldm(sb + (kc % 3) * STAGE_B, wm, wn, aoff, boff, acc);
    }

#pragma unroll
    for (int i = 0; i < 4; i++) {
        const int m_a = m0 + wm + 16 * i + gr;
#pragma unroll
        for (int j = 0; j < 4; j++) {
            const int col = n0 + wn + 8 * j + 2 * tig;
            *(float2*)&out[(size_t)m_a * E_ + col] =
                make_float2(acc[i][j][0], acc[i][j][1]);
            *(float2*)&out[(size_t)(m_a + 8) * E_ + col] =
                make_float2(acc[i][j][2], acc[i][j][3]);
        }
    }
}

// ---------------------------------------------------------------------------
// Tensor-core fused causal attention, cp.async double-buffered, ldmatrix frags.
// CTA = 128 Q-rows; 8 warps (m16 x n64); jt-steps of 64 K-columns.
// smem: 2 bufs x (Kh,Kl,Vh,Vl)[64][36]; P2h/P2l [128][36]; sl.
// Row stride 36 words (144B): ldmatrix phases hit banks 4r mod 32 -> all 32.
// ---------------------------------------------------------------------------
__global__ __launch_bounds__(256, 2) void attn_tc(float* __restrict__ attn_base)
{
    extern __shared__ uint32_t usm[];
    const uint32_t sb = smem_u32(usm);
    uint32_t* P2h = usm + 18432;
    uint32_t* P2l = usm + 23040;
    float*    sl  = (float*)(usm + 27648);

    const int bh = blockIdx.y;
    const int it = (int)gridDim.x - 1 - (int)blockIdx.x;   // heavy tiles first
    const int q0 = it * 128;
    const int tid = threadIdx.x, wid = tid >> 5, lane = tid & 31;
    const int gr = lane >> 2, tig = lane & 3;
    const int wm = wid * 16;

    const float* Qp = g_Q + (size_t)bh * L_ * D_;
    float* attn = attn_base + (size_t)bh * L_ * L_;

    // lane offsets (bytes) for ldmatrix into stride-36 buffers
    const uint32_t kvoff = (uint32_t)(((8 * (lane >> 4) + (lane & 7)) * 36 +
                                       ((lane >> 3) & 1) * 4) * 4);
    const uint32_t poff  = (uint32_t)(((wm + (lane & 7) + 8 * ((lane >> 3) & 1)) * 36 +
                                       (lane >> 4) * 4) * 4);
    const uint32_t p2h_b = sb + 18432 * 4, p2l_b = sb + 23040 * 4;

    // Q A-fragments, pre-split packed bf16x2 (4 k16-chunks over D=64)
    uint32_t qh[4][4], ql[4][4];
    const int grow0 = q0 + wm + gr, grow1 = grow0 + 8;
#pragma unroll
    for (int kc = 0; kc < 4; kc++) {
        float2 q00 = *(const float2*)&Qp[(size_t)grow0 * D_ + kc * 16 + 2 * tig];
        float2 q10 = *(const float2*)&Qp[(size_t)grow1 * D_ + kc * 16 + 2 * tig];
        float2 q01 = *(const float2*)&Qp[(size_t)grow0 * D_ + kc * 16 + 2 * tig + 8];
        float2 q11 = *(const float2*)&Qp[(size_t)grow1 * D_ + kc * 16 + 2 * tig + 8];
        split_pack(q00.x, q00.y, qh[kc][0], ql[kc][0]);
        split_pack(q10.x, q10.y, qh[kc][1], ql[kc][1]);
        split_pack(q01.x, q01.y, qh[kc][2], ql[kc][2]);
        split_pack(q11.x, q11.y, qh[kc][3], ql[kc][3]);
    }

    const int ntiles = 2 * it + 2;
    const float scale = 0.125f;

    auto issue = [&](int jt) {
        const uint32_t kbase = sb + (jt & 1) * 36864;
#pragma unroll
        for (int c = 0; c < 2; c++) {
            int s = c * 256 + tid;
            int r = s >> 3, seg = (s & 7) * 4;
            uint32_t doff = (uint32_t)(r * 36 + seg) * 4;
            size_t ksrc = ((size_t)bh * L_ + jt * 64 + r) * 32 + seg;
            size_t vsrc = ((size_t)bh * 64 + r) * (L_ / 2) + jt * 32 + seg;
            cp16(kbase + doff,         g_Khg + ksrc);
            cp16(kbase + 9216 + doff,  g_Klg + ksrc);
            cp16(kbase + 18432 + doff, g_Vph + vsrc);
            cp16(kbase + 27648 + doff, g_Vpl + vsrc);
        }
        cp_commit();
    };
    issue(0);

    float l0 = 0.f, l1 = 0.f;
    float oa[8][4] = {};

    for (int jt = 0; jt < ntiles; jt++) {
        cp_wait0();
        __syncthreads();
        if (jt + 1 < ntiles) issue(jt + 1);

        const uint32_t kh_b = sb + (jt & 1) * 36864;
        const uint32_t kl_b = kh_b + 9216;
        const uint32_t vh_b = kh_b + 18432;
        const uint32_t vl_b = kh_b + 27648;

        // QK + exp fused, nt-pairs; K B-frags via ldmatrix.x4
#pragma unroll
        for (int np = 0; np < 4; np++) {
            float sc[2][4] = {};
            const uint32_t rowb = (uint32_t)(16 * np * 36 * 4) + kvoff;
#pragma unroll
            for (int kc = 0; kc < 4; kc++) {
                uint32_t kh4[4], kl4[4];
                ldm4(kh4, kh_b + rowb + kc * 32);
                ldm4(kl4, kl_b + rowb + kc * 32);
                mma_bf16(sc[0], qh[kc], kh4);
                mma_bf16(sc[0], qh[kc], kl4);
                mma_bf16(sc[0], ql[kc], kh4);
                mma_bf16(sc[1], qh[kc], kh4 + 2);
                mma_bf16(sc[1], qh[kc], kl4 + 2);
                mma_bf16(sc[1], ql[kc], kh4 + 2);
            }
#pragma unroll
            for (int u = 0; u < 2; u++) {
                const int nt = 2 * np + u;
                int jc = jt * 64 + nt * 8 + 2 * tig;
                float p0 = __expf(sc[u][0] * scale); if (jc     > grow0) p0 = 0.f;
                float p1 = __expf(sc[u][1] * scale); if (jc + 1 > grow0) p1 = 0.f;
                float p2 = __expf(sc[u][2] * scale); if (jc     > grow1) p2 = 0.f;
                float p3 = __expf(sc[u][3] * scale); if (jc + 1 > grow1) p3 = 0.f;
                l0 += p0 + p1;
                l1 += p2 + p3;
                uint32_t h, l;
                split_pack(p0, p1, h, l);
                P2h[(wm + gr) * 36 + nt * 4 + tig] = h;
                P2l[(wm + gr) * 36 + nt * 4 + tig] = l;
                split_pack(p2, p3, h, l);
                P2h[(wm + gr + 8) * 36 + nt * 4 + tig] = h;
                P2l[(wm + gr + 8) * 36 + nt * 4 + tig] = l;
                *(float2*)&attn[(size_t)grow0 * L_ + jc] = make_float2(p0, p1);
                *(float2*)&attn[(size_t)grow1 * L_ + jc] = make_float2(p2, p3);
            }
        }
        __syncwarp();   // P2 rows are warp-private; ldmatrix reads across lanes

        // O += P V; P A-frags and V B-frags via ldmatrix.x4
#pragma unroll
        for (int kc = 0; kc < 4; kc++) {
            uint32_t ph[4], plo[4];
            ldm4(ph,  p2h_b + poff + kc * 32);
            ldm4(plo, p2l_b + poff + kc * 32);
#pragma unroll
            for (int np = 0; np < 4; np++) {
                const uint32_t rowb = (uint32_t)(16 * np * 36 * 4) + kvoff;
                uint32_t vh4[4], vl4[4];
                ldm4(vh4, vh_b + rowb + kc * 32);
                ldm4(vl4, vl_b + rowb + kc * 32);
                mma_bf16(oa[2 * np], ph, vh4);
                mma_bf16(oa[2 * np], ph, vl4);
                mma_bf16(oa[2 * np], plo, vh4);
                mma_bf16(oa[2 * np + 1], ph, vh4 + 2);
                mma_bf16(oa[2 * np + 1], ph, vl4 + 2);
                mma_bf16(oa[2 * np + 1], plo, vh4 + 2);
            }
        }
    }

    // row sums: reduce lane partials over the quad
    l0 += __shfl_xor_sync(0xffffffffu, l0, 1);
    l0 += __shfl_xor_sync(0xffffffffu, l0, 2);
    l1 += __shfl_xor_sync(0xffffffffu, l1, 1);
    l1 += __shfl_xor_sync(0xffffffffu, l1, 2);
    const float inv0 = 1.f / l0, inv1 = 1.f / l1;
    if (tig == 0) {
        sl[wm + gr] = inv0;
        sl[wm + gr + 8] = inv1;
    }
    // normalized O -> packed global (feeds outproj cp.async)
#pragma unroll
    for (int nt = 0; nt < 8; nt++) {
        uint32_t h, l;
        split_pack(oa[nt][0] * inv0, oa[nt][1] * inv0, h, l);
        size_t ia = ((size_t)bh * L_ + grow0) * 32 + nt * 4 + tig;
        g_Ohh[ia] = h; g_Ohl[ia] = l;
        split_pack(oa[nt][2] * inv1, oa[nt][3] * inv1, h, l);
        size_t ib = ((size_t)bh * L_ + grow1) * 32 + nt * 4 + tig;
        g_Ohh[ib] = h; g_Ohl[ib] = l;
    }
    __syncthreads();   // sl visible; all P gmem writes done CTA-wide

    // normalize lower tiles in place; zero-fill upper triangle
    for (int j2 = 0; j2 < ntiles; j2++) {
#pragma unroll
        for (int c = 0; c < 8; c++) {
            int id = c * 256 + tid;
            int r = id >> 4, c4 = (id & 15) << 2;
            float inv = sl[r];
            float* p = &attn[(size_t)(q0 + r) * L_ + j2 * 64 + c4];
            float4 v = *(float4*)p;
            v.x *= inv; v.y *= inv; v.z *= inv; v.w *= inv;
            *(float4*)p = v;
        }
    }
    const float4 z4 = make_float4(0.f, 0.f, 0.f, 0.f);
    for (int j2 = ntiles; j2 < L_ / 64; j2++) {
#pragma unroll
        for (int c = 0; c < 8; c++) {
            int id = c * 256 + tid;
            int r = id >> 4, c4 = (id & 15) << 2;
            *(float4*)&attn[(size_t)(q0 + r) * L_ + j2 * 64 + c4] = z4;
        }
    }
}

constexpr int ATTN_SMEM = (27648 + 128) * 4;   // 111104 B

// ---------------------------------------------------------------------------
extern "C" void kernel_launch(void* const* d_in, const int* in_sizes, int n_in,
                              void* d_out, int out_size)
{
    const float* qkv[3] = {nullptr, nullptr, nullptr};
    const float* Ws[4]  = {nullptr, nullptr, nullptr, nullptr};
    int nqkv = 0, nw = 0;
    for (int i = 0; i < n_in; i++) {
        if (in_sizes[i] == NTOK * E_) { if (nqkv < 3) qkv[nqkv++] = (const float*)d_in[i]; }
        else if (in_sizes[i] == E_ * E_) { if (nw < 4) Ws[nw++] = (const float*)d_in[i]; }
    }
    float* out  = (float*)d_out;
    float* attn = out + (size_t)B_ * L_ * E_;

    cudaFuncSetAttribute(proj_tc, cudaFuncAttributeMaxDynamicSharedMemorySize, GEMM_SMEM);
    cudaFuncSetAttribute(outproj_tc, cudaFuncAttributeMaxDynamicSharedMemorySize, GEMM_SMEM);
    cudaFuncSetAttribute(attn_tc, cudaFuncAttributeMaxDynamicSharedMemorySize, ATTN_SMEM);

    for (int i = 0; i < 3; i++)
        pack_kernel<<<NTOK * E_ / 8 / 256, 256>>>((const float4*)qkv[i], i);
    for (int i = 0; i < 4; i++)
        pack_kernel<<<E_ * E_ / 8 / 256, 256>>>((const float4*)Ws[i], 3 + i);

    proj_tc<<<dim3(E_ / 128, NTOK / 128, 3), 256, GEMM_SMEM>>>();
    vpack_kernel<<<dim3(L_ / 64, BH), 256>>>();
    attn_tc<<<dim3(L_ / 128, BH), 256, ATTN_SMEM>>>(attn);
    outproj_tc<<<dim3(E_ / 128, NTOK / 128), 256, GEMM_SMEM>>>(out);
}

// round 13
// speedup vs baseline: 2.2266x; 1.0986x over previous
#include <cuda_runtime.h>
#include <cstdint>

// ---------------------------------------------------------------------------
// MHA forward: out = (softmax_causal(QK^T/sqrt(D)) V) Wo^T,  also emit attn.
// B=4, L=2048, E=1024, H=16, D=64.
// d_out layout: [out: B*L*E floats][attn: B*H*L*L floats]
// 3xBF16 m16n8k16 everywhere; operands pre-packed bf16 hi/lo in gmem;
// ldmatrix fragment loads. R13: BK=32 2-stage GEMMs (half the syncs),
// attention zero-fill hoisted before mainloop + reverse-order normalize,
// pack launches merged to 3 (puts attn_tc at ncu's -s 5 capture slot).
// ---------------------------------------------------------------------------

constexpr int B_ = 4, L_ = 2048, E_ = 1024, H_ = 16, D_ = 64;
constexpr int BH   = B_ * H_;     // 64
constexpr int NTOK = B_ * L_;     // 8192

// fp32 scratch
__device__ float g_Q[BH * L_ * D_];
__device__ float g_V[BH * L_ * D_];
// packed bf16 hi/lo operands
__device__ uint32_t g_inh[3 * NTOK * E_ / 2], g_inl[3 * NTOK * E_ / 2];
__device__ uint32_t g_Wh[4 * E_ * E_ / 2],   g_Wl[4 * E_ * E_ / 2];
__device__ uint32_t g_Khg[BH * L_ * D_ / 2], g_Klg[BH * L_ * D_ / 2];
__device__ uint32_t g_Vph[BH * D_ * L_ / 2], g_Vpl[BH * D_ * L_ / 2];
__device__ uint32_t g_Ohh[BH * L_ * D_ / 2], g_Ohl[BH * L_ * D_ / 2];

// ---------------------------------------------------------------------------
__device__ __forceinline__ uint32_t pack2(float x0, float x1) {
    uint32_t r;
    asm("cvt.rn.bf16x2.f32 %0, %1, %2;" : "=r"(r) : "f"(x1), "f"(x0));
    return r;
}
__device__ __forceinline__ void split_pack(float x0, float x1,
                                           uint32_t& h, uint32_t& l) {
    h = pack2(x0, x1);
    float h0 = __uint_as_float(h << 16);
    float h1 = __uint_as_float(h & 0xffff0000u);
    l = pack2(x0 - h0, x1 - h1);
}
__device__ __forceinline__ void mma_bf16(float* c, const uint32_t* a,
                                         const uint32_t* b) {
    asm volatile(
        "mma.sync.aligned.m16n8k16.row.col.f32.bf16.bf16.f32 "
        "{%0,%1,%2,%3}, {%4,%5,%6,%7}, {%8,%9}, {%0,%1,%2,%3};"
        : "+f"(c[0]), "+f"(c[1]), "+f"(c[2]), "+f"(c[3])
        : "r"(a[0]), "r"(a[1]), "r"(a[2]), "r"(a[3]), "r"(b[0]), "r"(b[1]));
}
__device__ __forceinline__ void ldm4(uint32_t* r, uint32_t a) {
    asm volatile("ldmatrix.sync.aligned.m8n8.x4.shared.b16 {%0,%1,%2,%3}, [%4];"
        : "=r"(r[0]), "=r"(r[1]), "=r"(r[2]), "=r"(r[3]) : "r"(a));
}
__device__ __forceinline__ uint32_t smem_u32(const void* p) {
    uint32_t a;
    asm("{ .reg .u64 t; cvta.to.shared.u64 t, %1; cvt.u32.u64 %0, t; }"
        : "=r"(a) : "l"(p));
    return a;
}
__device__ __forceinline__ void cp16(uint32_t dst, const void* src) {
    asm volatile("cp.async.cg.shared.global [%0], [%1], 16;"
                 :: "r"(dst), "l"(src) : "memory");
}
__device__ __forceinline__ void cp_commit() {
    asm volatile("cp.async.commit_group;" ::: "memory");
}
__device__ __forceinline__ void cp_wait0() {
    asm volatile("cp.async.wait_group 0;" ::: "memory");
}

// ---------------------------------------------------------------------------
// prep: pack input z and W z (z==2 also packs Wo) into bf16 hi/lo.
// ---------------------------------------------------------------------------
constexpr int IN8 = NTOK * E_ / 8;   // float4-pairs per input tensor
constexpr int W8  = E_ * E_ / 8;

__global__ __launch_bounds__(256) void pack_combo(
    const float4* __restrict__ in_src, const float4* __restrict__ w_src,
    const float4* __restrict__ w2_src, int z)
{
    int g = blockIdx.x * 256 + threadIdx.x;
    const float4* src; uint4* dh; uint4* dl; int idx;
    if (g < IN8) {
        src = in_src; idx = g;
        dh = (uint4*)g_inh + (size_t)z * IN8 + idx;
        dl = (uint4*)g_inl + (size_t)z * IN8 + idx;
    } else if (g < IN8 + W8) {
        src = w_src; idx = g - IN8;
        dh = (uint4*)g_Wh + (size_t)z * W8 + idx;
        dl = (uint4*)g_Wl + (size_t)z * W8 + idx;
    } else if (w2_src != nullptr && g < IN8 + 2 * W8) {
        src = w2_src; idx = g - IN8 - W8;
        dh = (uint4*)g_Wh + (size_t)3 * W8 + idx;
        dl = (uint4*)g_Wl + (size_t)3 * W8 + idx;
    } else return;
    float4 a = src[2 * idx], b = src[2 * idx + 1];
    uint4 h, l;
    split_pack(a.x, a.y, h.x, l.x);
    split_pack(a.z, a.w, h.y, l.y);
    split_pack(b.x, b.y, h.z, l.z);
    split_pack(b.z, b.w, h.w, l.w);
    *dh = h; *dl = l;
}

// ---------------------------------------------------------------------------
// prep2: transpose-pack V -> g_Vp [bh][D][L/2] words.
// ---------------------------------------------------------------------------
__global__ __launch_bounds__(256) void vpack_kernel()
{
    __shared__ float t[64][65];
    const int jt = blockIdx.x, bh = blockIdx.y, tid = threadIdx.x;
    const float* Vp = g_V + ((size_t)bh * L_ + jt * 64) * D_;
#pragma unroll
    for (int c = 0; c < 4; c++) {
        int id = c * 256 + tid;
        int r = id >> 4, d4 = (id & 15) << 2;
        float4 v = *(const float4*)&Vp[(size_t)r * D_ + d4];
        t[r][d4] = v.x; t[r][d4 + 1] = v.y; t[r][d4 + 2] = v.z; t[r][d4 + 3] = v.w;
    }
    __syncthreads();
    const int rp = tid & 31;
#pragma unroll
    for (int i = 0; i < 8; i++) {
        int d = (tid >> 5) + 8 * i;
        uint32_t h, l;
        split_pack(t[2 * rp][d], t[2 * rp + 1][d], h, l);
        size_t idx = ((size_t)bh * 64 + d) * (L_ / 2) + jt * 32 + rp;
        g_Vph[idx] = h;
        g_Vpl[idx] = l;
    }
}

// ---------------------------------------------------------------------------
// 3xBF16 GEMM body, BK=32 (2 k16 sub-chunks), 2-stage ping-pong.
// Packed smem [row][PSTR2] stride 20 words (80B): ldmatrix 8-row phases hit
// banks 20r mod 32 = {0,20,8,28,16,4,24,12} quads -> all 32, conflict-free.
// ---------------------------------------------------------------------------
constexpr int NKC2 = E_ / 32;     // 32 chunks
constexpr int PSTR2 = 20;
constexpr int ARR_B = 128 * PSTR2 * 4;             // 10240 per array
constexpr int STAGE_B = 4 * ARR_B;                 // 40960 (Ah,Al,Bh,Bl)
constexpr int GEMM_SMEM = 2 * STAGE_B;             // 81920

__device__ __forceinline__ uint32_t a_lane_off(int lane) {
    int row = (lane & 7) + ((lane >> 3) & 1) * 8;
    int cw  = (lane >> 4) * 4;
    return (uint32_t)((row * PSTR2 + cw) * 4);
}
__device__ __forceinline__ uint32_t b_lane_off(int lane) {
    int row = (lane & 7) + (lane >> 4) * 8;
    int cw  = ((lane >> 3) & 1) * 4;
    return (uint32_t)((row * PSTR2 + cw) * 4);
}

// one BK=32 chunk: 24 LDSM.x4 + 96 mma
__device__ __forceinline__ void mma_chunk32(uint32_t stage, int wm, int wn,
                                            uint32_t aoff, uint32_t boff,
                                            float acc[4][4][4]) {
#pragma unroll
    for (int kc2 = 0; kc2 < 2; kc2++) {
        const uint32_t ko = kc2 * 32;
        uint32_t ah[4][4], al[4][4], bh[4][2], bl[4][2];
#pragma unroll
        for (int i = 0; i < 4; i++) {
            uint32_t addr = stage + (uint32_t)((wm + 16 * i) * PSTR2 * 4) + aoff + ko;
            ldm4(ah[i], addr);
            ldm4(al[i], addr + ARR_B);
        }
#pragma unroll
        for (int jp = 0; jp < 2; jp++) {
            uint32_t addr = stage + 2 * ARR_B +
                            (uint32_t)((wn + 16 * jp) * PSTR2 * 4) + boff + ko;
            uint32_t th[4], tl[4];
            ldm4(th, addr);
            ldm4(tl, addr + ARR_B);
            bh[2 * jp][0] = th[0]; bh[2 * jp][1] = th[1];
            bh[2 * jp + 1][0] = th[2]; bh[2 * jp + 1][1] = th[3];
            bl[2 * jp][0] = tl[0]; bl[2 * jp][1] = tl[1];
            bl[2 * jp + 1][0] = tl[2]; bl[2 * jp + 1][1] = tl[3];
        }
#pragma unroll
        for (int j = 0; j < 4; j++)
#pragma unroll
            for (int i = 0; i < 4; i++) {
                mma_bf16(acc[i][j], ah[i], bh[j]);
                mma_bf16(acc[i][j], ah[i], bl[j]);
                mma_bf16(acc[i][j], al[i], bh[j]);
            }
    }
}

// ---------------------------------------------------------------------------
// Projection GEMM (BK=32, 2-stage). z: 0=Q (fp32), 1=K (packed), 2=V (fp32).
// ---------------------------------------------------------------------------
__global__ __launch_bounds__(256, 2) void proj_tc()
{
    extern __shared__ uint8_t gsm_raw[];
    const uint32_t sb = smem_u32(gsm_raw);
    const int z = blockIdx.z;
    const uint32_t* Xh = g_inh + (size_t)z * (NTOK * E_ / 2);
    const uint32_t* Xl = g_inl + (size_t)z * (NTOK * E_ / 2);
    const uint32_t* WhP = g_Wh + (size_t)z * (E_ * E_ / 2);
    const uint32_t* WlP = g_Wl + (size_t)z * (E_ * E_ / 2);

    const int tid = threadIdx.x, wid = tid >> 5, lane = tid & 31;
    const int gr = lane >> 2, tig = lane & 3;
    const int wm = (wid & 1) * 64, wn = (wid >> 1) * 32;
    const int m0 = blockIdx.y * 128, n0 = blockIdx.x * 128;
    const uint32_t aoff = a_lane_off(lane), boff = b_lane_off(lane);

    const int row = tid >> 1, half = tid & 1;
    const size_t srcA = (size_t)(m0 + row) * (E_ / 2) + half * 8;
    const size_t srcB = (size_t)(n0 + row) * (E_ / 2) + half * 8;
    const uint32_t dOff = (uint32_t)(row * PSTR2 + half * 8) * 4;

    auto issue = [&](int kc) {
        const uint32_t base = sb + (kc & 1) * STAGE_B;
        const size_t o = (size_t)kc * 16;
        cp16(base + dOff,                Xh + srcA + o);
        cp16(base + dOff + 16,           Xh + srcA + o + 4);
        cp16(base + ARR_B + dOff,        Xl + srcA + o);
        cp16(base + ARR_B + dOff + 16,   Xl + srcA + o + 4);
        cp16(base + 2 * ARR_B + dOff,      WhP + srcB + o);
        cp16(base + 2 * ARR_B + dOff + 16, WhP + srcB + o + 4);
        cp16(base + 3 * ARR_B + dOff,      WlP + srcB + o);
        cp16(base + 3 * ARR_B + dOff + 16, WlP + srcB + o + 4);
        cp_commit();
    };
    issue(0);

    float acc[4][4][4] = {};
    for (int kc = 0; kc < NKC2; kc++) {
        cp_wait0();
        __syncthreads();
        if (kc + 1 < NKC2) issue(kc + 1);
        mma_chunk32(sb + (kc & 1) * STAGE_B, wm, wn, aoff, boff, acc);
    }

#pragma unroll
    for (int i = 0; i < 4; i++) {
        const int m_a = m0 + wm + 16 * i + gr;
        const int m_b = m_a + 8;
        const int ba = m_a >> 11, la = m_a & (L_ - 1);
        const int bb = m_b >> 11, lb = m_b & (L_ - 1);
#pragma unroll
        for (int j = 0; j < 4; j++) {
            const int col = n0 + wn + 8 * j + 2 * tig;
            const int hg = col >> 6, d = col & 63;
            if (z == 1) {   // K: write packed
                uint32_t ph, pl;
                size_t ia = ((size_t)(ba * H_ + hg) * L_ + la) * 32 + (d >> 1);
                split_pack(acc[i][j][0], acc[i][j][1], ph, pl);
                g_Khg[ia] = ph; g_Klg[ia] = pl;
                size_t ib = ((size_t)(bb * H_ + hg) * L_ + lb) * 32 + (d >> 1);
                split_pack(acc[i][j][2], acc[i][j][3], ph, pl);
                g_Khg[ib] = ph; g_Klg[ib] = pl;
            } else {        // Q or V: fp32
                float* Out = (z == 0) ? g_Q : g_V;
                *(float2*)&Out[((size_t)(ba * H_ + hg) * L_ + la) * D_ + d] =
                    make_float2(acc[i][j][0], acc[i][j][1]);
                *(float2*)&Out[((size_t)(bb * H_ + hg) * L_ + lb) * D_ + d] =
                    make_float2(acc[i][j][2], acc[i][j][3]);
            }
        }
    }
}

// ---------------------------------------------------------------------------
// Output projection (BK=32, 2-stage): A = packed Oh, B = packed Wo.
// ---------------------------------------------------------------------------
__global__ __launch_bounds__(256, 2) void outproj_tc(float* __restrict__ out)
{
    extern __shared__ uint8_t gsm_raw[];
    const uint32_t sb = smem_u32(gsm_raw);
    const uint32_t* WhP = g_Wh + (size_t)3 * (E_ * E_ / 2);
    const uint32_t* WlP = g_Wl + (size_t)3 * (E_ * E_ / 2);

    const int tid = threadIdx.x, wid = tid >> 5, lane = tid & 31;
    const int gr = lane >> 2, tig = lane & 3;
    const int wm = (wid & 1) * 64, wn = (wid >> 1) * 32;
    const int m0 = blockIdx.y * 128, n0 = blockIdx.x * 128;
    const uint32_t aoff = a_lane_off(lane), boff = b_lane_off(lane);

    const int row = tid >> 1, half = tid & 1;
    const int m = m0 + row, bb_ = m >> 11, ll = m & (L_ - 1);
    const size_t srcB = (size_t)(n0 + row) * (E_ / 2) + half * 8;
    const uint32_t dOff = (uint32_t)(row * PSTR2 + half * 8) * 4;

    auto issue = [&](int kc) {
        const uint32_t base = sb + (kc & 1) * STAGE_B;
        const int hg = kc >> 1;                       // head = kc*32/64
        const int w0 = (kc & 1) * 16 + half * 8;      // word within head row
        const size_t sa = ((size_t)(bb_ * H_ + hg) * L_ + ll) * 32 + w0;
        const size_t ob = (size_t)kc * 16;
        cp16(base + dOff,                g_Ohh + sa);
        cp16(base + dOff + 16,           g_Ohh + sa + 4);
        cp16(base + ARR_B + dOff,        g_Ohl + sa);
        cp16(base + ARR_B + dOff + 16,   g_Ohl + sa + 4);
        cp16(base + 2 * ARR_B + dOff,      WhP + srcB + ob);
        cp16(base + 2 * ARR_B + dOff + 16, WhP + srcB + ob + 4);
        cp16(base + 3 * ARR_B + dOff,      WlP + srcB + ob);
        cp16(base + 3 * ARR_B + dOff + 16, WlP + srcB + ob + 4);
        cp_commit();
    };
    issue(0);

    float acc[4][4][4] = {};
    for (int kc = 0; kc < NKC2; kc++) {
        cp_wait0();
        __syncthreads();
        if (kc + 1 < NKC2) issue(kc + 1);
        mma_chunk32(sb + (kc & 1) * STAGE_B, wm, wn, aoff, boff, acc);
    }

#pragma unroll
    for (int i = 0; i < 4; i++) {
        const int m_a = m0 + wm + 16 * i + gr;
#pragma unroll
        for (int j = 0; j < 4; j++) {
            const int col = n0 + wn + 8 * j + 2 * tig;
            *(float2*)&out[(size_t)m_a * E_ + col] =
                make_float2(acc[i][j][0], acc[i][j][1]);
            *(float2*)&out[(size_t)(m_a + 8) * E_ + col] =
                make_float2(acc[i][j][2], acc[i][j][3]);
        }
    }
}

// ---------------------------------------------------------------------------
// Tensor-core fused causal attention, cp.async double-buffered, ldmatrix frags.
// R13: zero-fill hoisted before mainloop; normalize walks tiles in reverse.
// ---------------------------------------------------------------------------
__global__ __launch_bounds__(256, 2) void attn_tc(float* __restrict__ attn_base)
{
    extern __shared__ uint32_t usm[];
    const uint32_t sb = smem_u32(usm);
    uint32_t* P2h = usm + 18432;
    uint32_t* P2l = usm + 23040;
    float*    sl  = (float*)(usm + 27648);

    const int bh = blockIdx.y;
    const int it = (int)gridDim.x - 1 - (int)blockIdx.x;   // heavy tiles first
    const int q0 = it * 128;
    const int tid = threadIdx.x, wid = tid >> 5, lane = tid & 31;
    const int gr = lane >> 2, tig = lane & 3;
    const int wm = wid * 16;

    const float* Qp = g_Q + (size_t)bh * L_ * D_;
    float* attn = attn_base + (size_t)bh * L_ * L_;

    const uint32_t kvoff = (uint32_t)(((8 * (lane >> 4) + (lane & 7)) * 36 +
                                       ((lane >> 3) & 1) * 4) * 4);
    const uint32_t poff  = (uint32_t)(((wm + (lane & 7) + 8 * ((lane >> 3) & 1)) * 36 +
                                       (lane >> 4) * 4) * 4);
    const uint32_t p2h_b = sb + 18432 * 4, p2l_b = sb + 23040 * 4;

    const int ntiles = 2 * it + 2;
    const float scale = 0.125f;

    auto issue = [&](int jt) {
        const uint32_t kbase = sb + (jt & 1) * 36864;
#pragma unroll
        for (int c = 0; c < 2; c++) {
            int s = c * 256 + tid;
            int r = s >> 3, seg = (s & 7) * 4;
            uint32_t doff = (uint32_t)(r * 36 + seg) * 4;
            size_t ksrc = ((size_t)bh * L_ + jt * 64 + r) * 32 + seg;
            size_t vsrc = ((size_t)bh * 64 + r) * (L_ / 2) + jt * 32 + seg;
            cp16(kbase + doff,         g_Khg + ksrc);
            cp16(kbase + 9216 + doff,  g_Klg + ksrc);
            cp16(kbase + 18432 + doff, g_Vph + vsrc);
            cp16(kbase + 27648 + doff, g_Vpl + vsrc);
        }
        cp_commit();
    };
    issue(0);

    // Q A-fragments, pre-split packed bf16x2
    uint32_t qh[4][4], ql[4][4];
    const int grow0 = q0 + wm + gr, grow1 = grow0 + 8;
#pragma unroll
    for (int kc = 0; kc < 4; kc++) {
        float2 q00 = *(const float2*)&Qp[(size_t)grow0 * D_ + kc * 16 + 2 * tig];
        float2 q10 = *(const float2*)&Qp[(size_t)grow1 * D_ + kc * 16 + 2 * tig];
        float2 q01 = *(const float2*)&Qp[(size_t)grow0 * D_ + kc * 16 + 2 * tig + 8];
        float2 q11 = *(const float2*)&Qp[(size_t)grow1 * D_ + kc * 16 + 2 * tig + 8];
        split_pack(q00.x, q00.y, qh[kc][0], ql[kc][0]);
        split_pack(q10.x, q10.y, qh[kc][1], ql[kc][1]);
        split_pack(q01.x, q01.y, qh[kc][2], ql[kc][2]);
        split_pack(q11.x, q11.y, qh[kc][3], ql[kc][3]);
    }

    // zero-fill upper triangle EARLY: stores drain behind the mainloop
    {
        const float4 z4 = make_float4(0.f, 0.f, 0.f, 0.f);
        for (int j2 = ntiles; j2 < L_ / 64; j2++) {
#pragma unroll
            for (int c = 0; c < 8; c++) {
                int id = c * 256 + tid;
                int r = id >> 4, c4 = (id & 15) << 2;
                *(float4*)&attn[(size_t)(q0 + r) * L_ + j2 * 64 + c4] = z4;
            }
        }
    }

    float l0 = 0.f, l1 = 0.f;
    float oa[8][4] = {};

    for (int jt = 0; jt < ntiles; jt++) {
        cp_wait0();
        __syncthreads();
        if (jt + 1 < ntiles) issue(jt + 1);

        const uint32_t kh_b = sb + (jt & 1) * 36864;
        const uint32_t kl_b = kh_b + 9216;
        const uint32_t vh_b = kh_b + 18432;
        const uint32_t vl_b = kh_b + 27648;

        // QK + exp fused, nt-pairs; K B-frags via ldmatrix.x4
#pragma unroll
        for (int np = 0; np < 4; np++) {
            float sc[2][4] = {};
            const uint32_t rowb = (uint32_t)(16 * np * 36 * 4) + kvoff;
#pragma unroll
            for (int kc = 0; kc < 4; kc++) {
                uint32_t kh4[4], kl4[4];
                ldm4(kh4, kh_b + rowb + kc * 32);
                ldm4(kl4, kl_b + rowb + kc * 32);
                mma_bf16(sc[0], qh[kc], kh4);
                mma_bf16(sc[0], qh[kc], kl4);
                mma_bf16(sc[0], ql[kc], kh4);
                mma_bf16(sc[1], qh[kc], kh4 + 2);
                mma_bf16(sc[1], qh[kc], kl4 + 2);
                mma_bf16(sc[1], ql[kc], kh4 + 2);
            }
#pragma unroll
            for (int u = 0; u < 2; u++) {
                const int nt = 2 * np + u;
                int jc = jt * 64 + nt * 8 + 2 * tig;
                float p0 = __expf(sc[u][0] * scale); if (jc     > grow0) p0 = 0.f;
                float p1 = __expf(sc[u][1] * scale); if (jc + 1 > grow0) p1 = 0.f;
                float p2 = __expf(sc[u][2] * scale); if (jc     > grow1) p2 = 0.f;
                float p3 = __expf(sc[u][3] * scale); if (jc + 1 > grow1) p3 = 0.f;
                l0 += p0 + p1;
                l1 += p2 + p3;
                uint32_t h, l;
                split_pack(p0, p1, h, l);
                P2h[(wm + gr) * 36 + nt * 4 + tig] = h;
                P2l[(wm + gr) * 36 + nt * 4 + tig] = l;
                split_pack(p2, p3, h, l);
                P2h[(wm + gr + 8) * 36 + nt * 4 + tig] = h;
                P2l[(wm + gr + 8) * 36 + nt * 4 + tig] = l;
                *(float2*)&attn[(size_t)grow0 * L_ + jc] = make_float2(p0, p1);
                *(float2*)&attn[(size_t)grow1 * L_ + jc] = make_float2(p2, p3);
            }
        }
        __syncwarp();   // P2 rows are warp-private

        // O += P V; P A-frags and V B-frags via ldmatrix.x4
#pragma unroll
        for (int kc = 0; kc < 4; kc++) {
            uint32_t ph[4], plo[4];
            ldm4(ph,  p2h_b + poff + kc * 32);
            ldm4(plo, p2l_b + poff + kc * 32);
#pragma unroll
            for (int np = 0; np < 4; np++) {
                const uint32_t rowb = (uint32_t)(16 * np * 36 * 4) + kvoff;
                uint32_t vh4[4], vl4[4];
                ldm4(vh4, vh_b + rowb + kc * 32);
                ldm4(vl4, vl_b + rowb + kc * 32);
                mma_bf16(oa[2 * np], ph, vh4);
                mma_bf16(oa[2 * np], ph, vl4);
                mma_bf16(oa[2 * np], plo, vh4);
                mma_bf16(oa[2 * np + 1], ph, vh4 + 2);
                mma_bf16(oa[2 * np + 1], ph, vl4 + 2);
                mma_bf16(oa[2 * np + 1], plo, vh4 + 2);
            }
        }
    }

    // row sums: reduce lane partials over the quad
    l0 += __shfl_xor_sync(0xffffffffu, l0, 1);
    l0 += __shfl_xor_sync(0xffffffffu, l0, 2);
    l1 += __shfl_xor_sync(0xffffffffu, l1, 1);
    l1 += __shfl_xor_sync(0xffffffffu, l1, 2);
    const float inv0 = 1.f / l0, inv1 = 1.f / l1;
    if (tig == 0) {
        sl[wm + gr] = inv0;
        sl[wm + gr + 8] = inv1;
    }
    // normalized O -> packed global (feeds outproj cp.async)
#pragma unroll
    for (int nt = 0; nt < 8; nt++) {
        uint32_t h, l;
        split_pack(oa[nt][0] * inv0, oa[nt][1] * inv0, h, l);
        size_t ia = ((size_t)bh * L_ + grow0) * 32 + nt * 4 + tig;
        g_Ohh[ia] = h; g_Ohl[ia] = l;
        split_pack(oa[nt][2] * inv1, oa[nt][3] * inv1, h, l);
        size_t ib = ((size_t)bh * L_ + grow1) * 32 + nt * 4 + tig;
        g_Ohh[ib] = h; g_Ohl[ib] = l;
    }
    __syncthreads();   // sl visible; all P gmem writes done CTA-wide

    // normalize lower tiles in place, most-recently-written (L2-hot) first
    for (int j2 = ntiles - 1; j2 >= 0; j2--) {
#pragma unroll
        for (int c = 0; c < 8; c++) {
            int id = c * 256 + tid;
            int r = id >> 4, c4 = (id & 15) << 2;
            float inv = sl[r];
            float* p = &attn[(size_t)(q0 + r) * L_ + j2 * 64 + c4];
            float4 v = *(float4*)p;
            v.x *= inv; v.y *= inv; v.z *= inv; v.w *= inv;
            *(float4*)p = v;
        }
    }
}

constexpr int ATTN_SMEM = (27648 + 128) * 4;   // 111104 B

// ---------------------------------------------------------------------------
extern "C" void kernel_launch(void* const* d_in, const int* in_sizes, int n_in,
                              void* d_out, int out_size)
{
    const float* qkv[3] = {nullptr, nullptr, nullptr};
    const float* Ws[4]  = {nullptr, nullptr, nullptr, nullptr};
    int nqkv = 0, nw = 0;
    for (int i = 0; i < n_in; i++) {
        if (in_sizes[i] == NTOK * E_) { if (nqkv < 3) qkv[nqkv++] = (const float*)d_in[i]; }
        else if (in_sizes[i] == E_ * E_) { if (nw < 4) Ws[nw++] = (const float*)d_in[i]; }
    }
    float* out  = (float*)d_out;
    float* attn = out + (size_t)B_ * L_ * E_;

    cudaFuncSetAttribute(proj_tc, cudaFuncAttributeMaxDynamicSharedMemorySize, GEMM_SMEM);
    cudaFuncSetAttribute(outproj_tc, cudaFuncAttributeMaxDynamicSharedMemorySize, GEMM_SMEM);
    cudaFuncSetAttribute(attn_tc, cudaFuncAttributeMaxDynamicSharedMemorySize, ATTN_SMEM);

    // 3 pack launches (z=2 also packs Wo) -> attn_tc is the 6th launch (ncu -s 5)
    pack_combo<<<(IN8 + W8 + 255) / 256, 256>>>(
        (const float4*)qkv[0], (const float4*)Ws[0], nullptr, 0);
    pack_combo<<<(IN8 + W8 + 255) / 256, 256>>>(
        (const float4*)qkv[1], (const float4*)Ws[1], nullptr, 1);
    pack_combo<<<(IN8 + 2 * W8 + 255) / 256, 256>>>(
        (const float4*)qkv[2], (const float4*)Ws[2], (const float4*)Ws[3], 2);

    proj_tc<<<dim3(E_ / 128, NTOK / 128, 3), 256, GEMM_SMEM>>>();
    vpack_kernel<<<dim3(L_ / 64, BH), 256>>>();
    attn_tc<<<dim3(L_ / 128, BH), 256, ATTN_SMEM>>>(attn);
    outproj_tc<<<dim3(E_ / 128, NTOK / 128), 256, GEMM_SMEM>>>(out);
}